// round 14
// baseline (speedup 1.0000x reference)
#include <cuda_runtime.h>
#include <cuda_bf16.h>
#include <mma.h>
#include <math.h>
#include <stdint.h>

using namespace nvcuda;

#define Bb 8
#define Nn 512
#define Ee 256
#define Hh 8
#define FFd 1024
#define TOPK 102
#define Mrows (Bb*Nn)   // 4096

// ---------------- device scratch ----------------
__device__ unsigned int  g_adjbits[Bb*Nn*16];
__device__ int           g_topkidx[Bb*Nn*104];   // after pack: idx | (spd<<16)
__device__ unsigned char g_spd[Bb*Nn*Nn];
__device__ float         g_score[Mrows];
__device__ __align__(16) float g_qkv[Mrows*768];
__device__ __align__(16) float g_y  [Mrows*Ee];
__device__ __align__(16) float g_x1 [Mrows*Ee];
__device__ __align__(16) float g_x2 [Mrows*Ee];

__device__ __align__(16) __nv_bfloat16 g_kb  [Mrows*Ee];
__device__ __align__(16) __nv_bfloat16 g_vb  [Mrows*Ee];
__device__ __align__(16) __nv_bfloat16 g_xh  [Mrows*Ee];
__device__ __align__(16) __nv_bfloat16 g_ctxh[Mrows*Ee],  g_ctxl[Mrows*Ee];
__device__ __align__(16) __nv_bfloat16 g_x1h [Mrows*Ee];
__device__ __align__(16) __nv_bfloat16 g_ffh [Mrows*FFd], g_ffl [Mrows*FFd];
__device__ __align__(16) __nv_bfloat16 g_wqkvh[768*256];
__device__ __align__(16) __nv_bfloat16 g_wouth[256*256],  g_woutl[256*256];
__device__ __align__(16) __nv_bfloat16 g_wff1h[1024*256];
__device__ __align__(16) __nv_bfloat16 g_wff2h[256*1024], g_wff2l[256*1024];

// ================= helpers =================
__device__ __forceinline__ uint32_t smem_to_u32(const void* p) {
    uint32_t a;
    asm("{ .reg .u64 t; cvta.to.shared.u64 t, %1; cvt.u32.u64 %0, t; }" : "=r"(a) : "l"(p));
    return a;
}
__device__ __forceinline__ void cpasync16(uint32_t sm, const void* g) {
    asm volatile("cp.async.cg.shared.global [%0], [%1], 16;" :: "r"(sm), "l"(g) : "memory");
}
__device__ __forceinline__ void split2(float a, float b, __nv_bfloat162& h, __nv_bfloat162& l) {
    h = __floats2bfloat162_rn(a, b);
    l = __floats2bfloat162_rn(a - __bfloat162float(h.x), b - __bfloat162float(h.y));
}

// ---------------- 0) fused fp32 -> bf16 convert (lo only where needed) --------------
__global__ void cvt_all(const float* __restrict__ x, const float* __restrict__ wqkv,
                        const float* __restrict__ wout, const float* __restrict__ wff1,
                        const float* __restrict__ wff2)
{
    int gid = blockIdx.x*256 + threadIdx.x;       // float4 index, total 458752
    const float* in; __nv_bfloat16 *hi, *lo = nullptr; int off;
    if      (gid < 262144) { in = x;    hi = g_xh;    off = gid; }
    else if (gid < 311296) { in = wqkv; hi = g_wqkvh; off = gid - 262144; }
    else if (gid < 327680) { in = wout; hi = g_wouth; lo = g_woutl; off = gid - 311296; }
    else if (gid < 393216) { in = wff1; hi = g_wff1h; off = gid - 327680; }
    else                   { in = wff2; hi = g_wff2h; lo = g_wff2l; off = gid - 393216; }
    float4 v = ((const float4*)in)[off];
    __nv_bfloat162 h0, l0, h1, l1;
    split2(v.x, v.y, h0, l0);
    split2(v.z, v.w, h1, l1);
    int i = off*4;
    *(__nv_bfloat162*)(hi + i)     = h0;
    *(__nv_bfloat162*)(hi + i + 2) = h1;
    if (lo) {
        *(__nv_bfloat162*)(lo + i)     = l0;
        *(__nv_bfloat162*)(lo + i + 2) = l1;
    }
}

// ---------------- 1) top-k (512 threads) ----------------------------------------------
__global__ void __launch_bounds__(512) topk_kernel(const float* __restrict__ adj)
{
    __shared__ unsigned long long keys[512];
    __shared__ unsigned int bw[16];
    const int row = blockIdx.x;
    const int tid = threadIdx.x;

    {
        unsigned int bits = __float_as_uint(adj[(size_t)row*512 + tid]);
        unsigned int ord  = bits ^ ((bits & 0x80000000u) ? 0xFFFFFFFFu : 0x80000000u);
        keys[tid] = ((unsigned long long)ord << 32) | (unsigned long long)(511 - tid);
    }
    if (tid < 16) bw[tid] = 0u;
    __syncthreads();

    for (int k = 2; k <= 512; k <<= 1) {
        for (int jj = k >> 1; jj > 0; jj >>= 1) {
            int i = tid;
            int ixj = i ^ jj;
            if (ixj > i) {
                unsigned long long a = keys[i], c = keys[ixj];
                bool up = ((i & k) == 0);
                if ((a > c) == up) { keys[i] = c; keys[ixj] = a; }
            }
            __syncthreads();
        }
    }
    if (tid < TOPK) {
        int j = 511 - (int)(keys[410 + tid] & 0xFFFFFFFFull);
        atomicOr(&bw[j >> 5], 1u << (j & 31));
        g_topkidx[(size_t)row*104 + tid] = j;
    }
    __syncthreads();
    if (tid < 16) g_adjbits[row*16 + tid] = bw[tid];
}

// ---------------- 2) BFS: 16 warps = 16 independent sources, smem adjacency ---------
__global__ void __launch_bounds__(512) bfs16_kernel()
{
    __shared__ unsigned int adjs[512*17];
    const int tid = threadIdx.x, lane = tid & 31, w = tid >> 5;
    const int blk = blockIdx.x;                 // 0..255
    const int b = blk >> 5;
    const int s0 = (blk & 31) << 4;

    #pragma unroll
    for (int k = 0; k < 16; k++)
        adjs[tid*17 + k] = g_adjbits[((size_t)(b*Nn) + tid)*16 + k];
    __syncthreads();

    const int src = s0 + w;
    const size_t spdbase = (size_t)(b*Nn + src) * Nn;

    for (int i = lane; i < 128; i += 32)
        ((unsigned int*)(g_spd + spdbase))[i] = 0u;
    __syncwarp();
    if (lane == 0) g_spd[spdbase + src] = 1;

    unsigned int visw = 0u, frow = 0u;
    if (lane < 16) {
        frow = (lane == (src >> 5)) ? (1u << (src & 31)) : 0u;
        visw = frow;
    }

    for (int level = 1; level <= 10; level++) {
        unsigned int acc[16];
        #pragma unroll
        for (int k = 0; k < 16; k++) acc[k] = 0u;

        #pragma unroll 1
        for (int wd = 0; wd < 16; wd++) {
            unsigned int bits = __shfl_sync(0xFFFFFFFFu, frow, wd);
            if ((bits >> lane) & 1u) {
                const unsigned int* row = &adjs[(wd*32 + lane)*17];
                #pragma unroll
                for (int k = 0; k < 16; k++) acc[k] |= row[k];
            }
        }
        unsigned int nv = 0u;
        #pragma unroll
        for (int k = 0; k < 16; k++) {
            unsigned int full = __reduce_or_sync(0xFFFFFFFFu, acc[k]);
            if (lane == k) nv = full & ~visw;
        }
        if (lane < 16) { visw |= nv; frow = nv; } else frow = 0u;

        unsigned int any = __reduce_or_sync(0xFFFFFFFFu, (lane < 16) ? nv : 0u);
        if (!any) break;

        unsigned char dval = (unsigned char)((level + 1 < 6) ? level + 1 : 6);
        #pragma unroll 1
        for (int wd = 0; wd < 16; wd++) {
            unsigned int bits = __shfl_sync(0xFFFFFFFFu, frow, wd);
            if ((bits >> lane) & 1u)
                g_spd[spdbase + wd*32 + lane] = dval;
        }
    }
}

// ---------------- 2b) pack spd into topkidx (head-invariant, gather once) -----------
__global__ void __launch_bounds__(128) pack_kernel()
{
    const int row = blockIdx.x;           // 0..4095
    const int t = threadIdx.x;
    if (t < TOPK) {
        int j = g_topkidx[(size_t)row*104 + t];
        int spd = g_spd[(size_t)row*Nn + j];
        g_topkidx[(size_t)row*104 + t] = j | (spd << 16);
    }
}

// ---------------- 3) pipelined bf16 wmma GEMM: 4 buffers, 1 sync/chunk ---------------
template<int BM, int BN, int WR, int WC, int TERMS>
__global__ void __launch_bounds__(WR*WC*32, 2) gemm_t(
    const __nv_bfloat16* __restrict__ Ah, const __nv_bfloat16* __restrict__ Al,
    const __nv_bfloat16* __restrict__ Wh, const __nv_bfloat16* __restrict__ Wl,
    const float* __restrict__ bias, const float* __restrict__ res,
    float* __restrict__ Cf, __nv_bfloat16* __restrict__ Ch, __nv_bfloat16* __restrict__ Cl,
    __nv_bfloat16* __restrict__ Kb, __nv_bfloat16* __restrict__ Vb,
    int K, int Ndim, int relu)
{
    constexpr int WARPS = WR*WC, THREADS = WARPS*32;
    constexpr int WM = BM/WR, WN = BN/WC, FR = WM/16, FC = WN/16;
    static_assert(WN == 32, "epilogue assumes WN==32");
    constexpr int NM = (TERMS == 3) ? 2 : 1;
    constexpr int AROWS = BM*40;
    constexpr int WROWS = BN*40;
    constexpr int BUFB = (NM*AROWS + NM*WROWS)*2;
    constexpr int SLOTS = (NM*BM + NM*BN)*2;

    extern __shared__ __align__(128) char s[];
    const uint32_t sb = smem_to_u32(s);
    const int tid = threadIdx.x, wid = tid >> 5, lane = tid & 31;
    const int m0 = blockIdx.y * BM, n0 = blockIdx.x * BN;
    const int wr = wid / WC, wc = wid % WC;

    wmma::fragment<wmma::accumulator,16,16,16,float> acc[FR][FC];
    #pragma unroll
    for (int r = 0; r < FR; r++)
        #pragma unroll
        for (int t = 0; t < FC; t++) wmma::fill_fragment(acc[r][t], 0.f);

    auto stage = [&](int c, int buf) {
        const int kk = c * 32;
        #pragma unroll
        for (int sl = tid; sl < SLOTS; sl += THREADS) {
            int half = sl & 1, rowid = sl >> 1;
            const __nv_bfloat16* src; uint32_t dst;
            if (rowid < BM) {
                src = Ah + (size_t)(m0 + rowid)*K;
                dst = sb + buf*BUFB + rowid*80;
            } else if (TERMS == 3 && rowid < 2*BM) {
                int r2 = rowid - BM;
                src = Al + (size_t)(m0 + r2)*K;
                dst = sb + buf*BUFB + AROWS*2 + r2*80;
            } else if (rowid < NM*BM + BN) {
                int r2 = rowid - NM*BM;
                src = Wh + (size_t)(n0 + r2)*K;
                dst = sb + buf*BUFB + NM*AROWS*2 + r2*80;
            } else {
                int r2 = rowid - NM*BM - BN;
                src = Wl + (size_t)(n0 + r2)*K;
                dst = sb + buf*BUFB + NM*AROWS*2 + WROWS*2 + r2*80;
            }
            cpasync16(dst + half*32,      src + kk + half*16);
            cpasync16(dst + half*32 + 16, src + kk + half*16 + 8);
        }
        asm volatile("cp.async.commit_group;" ::: "memory");
    };

    const int nc = K >> 5;
    stage(0, 0);
    stage(1, 1);

    for (int c = 0; c < nc; c++) {
        if (c + 2 < nc) stage(c + 2, (c + 2) & 3);
        if (c + 2 < nc)       asm volatile("cp.async.wait_group 2;" ::: "memory");
        else if (c + 1 < nc)  asm volatile("cp.async.wait_group 1;" ::: "memory");
        else                  asm volatile("cp.async.wait_group 0;" ::: "memory");
        __syncthreads();

        const __nv_bfloat16* sAh = (const __nv_bfloat16*)(s + (c & 3)*BUFB);
        const __nv_bfloat16* sAl = sAh + AROWS;
        const __nv_bfloat16* sWh = sAh + NM*AROWS;
        const __nv_bfloat16* sWl = sWh + WROWS;

        #pragma unroll
        for (int ks = 0; ks < 2; ks++) {
            wmma::fragment<wmma::matrix_a,16,16,16,__nv_bfloat16,wmma::row_major> af[FR];
            wmma::fragment<wmma::matrix_b,16,16,16,__nv_bfloat16,wmma::col_major> bf_[FC];
            // term 1: Ah * Wh
            #pragma unroll
            for (int r = 0; r < FR; r++)
                wmma::load_matrix_sync(af[r], sAh + (wr*WM + r*16)*40 + ks*16, 40);
            #pragma unroll
            for (int t = 0; t < FC; t++)
                wmma::load_matrix_sync(bf_[t], sWh + (wc*WN + t*16)*40 + ks*16, 40);
            #pragma unroll
            for (int r = 0; r < FR; r++)
                #pragma unroll
                for (int t = 0; t < FC; t++) wmma::mma_sync(acc[r][t], af[r], bf_[t], acc[r][t]);
            if (TERMS == 3) {
                // term 2: Ah * Wl
                #pragma unroll
                for (int t = 0; t < FC; t++)
                    wmma::load_matrix_sync(bf_[t], sWl + (wc*WN + t*16)*40 + ks*16, 40);
                #pragma unroll
                for (int r = 0; r < FR; r++)
                    #pragma unroll
                    for (int t = 0; t < FC; t++) wmma::mma_sync(acc[r][t], af[r], bf_[t], acc[r][t]);
                // term 3: Al * Wh
                #pragma unroll
                for (int r = 0; r < FR; r++)
                    wmma::load_matrix_sync(af[r], sAl + (wr*WM + r*16)*40 + ks*16, 40);
                #pragma unroll
                for (int t = 0; t < FC; t++)
                    wmma::load_matrix_sync(bf_[t], sWh + (wc*WN + t*16)*40 + ks*16, 40);
                #pragma unroll
                for (int r = 0; r < FR; r++)
                    #pragma unroll
                    for (int t = 0; t < FC; t++) wmma::mma_sync(acc[r][t], af[r], bf_[t], acc[r][t]);
            }
        }
    }
    __syncthreads();

    // epilogue
    float* ep = (float*)s + wid*16*40;
    const int rr = lane & 15, hf = lane >> 4;
    #pragma unroll
    for (int rt = 0; rt < FR; rt++) {
        wmma::store_matrix_sync(ep,      acc[rt][0], 40, wmma::mem_row_major);
        wmma::store_matrix_sync(ep + 16, acc[rt][1], 40, wmma::mem_row_major);
        __syncwarp();
        const int m = m0 + wr*WM + rt*16 + rr;
        #pragma unroll
        for (int q = 0; q < 4; q++) {
            const int n = n0 + wc*WN + hf*16 + q*4;
            float4 v = *(float4*)&ep[rr*40 + hf*16 + q*4];
            float4 bv = *(const float4*)&bias[n];
            v.x += bv.x; v.y += bv.y; v.z += bv.z; v.w += bv.w;
            if (res) {
                float4 rv = *(const float4*)&res[(size_t)m*Ndim + n];
                v.x += rv.x; v.y += rv.y; v.z += rv.z; v.w += rv.w;
            }
            if (relu) {
                v.x = fmaxf(v.x, 0.f); v.y = fmaxf(v.y, 0.f);
                v.z = fmaxf(v.z, 0.f); v.w = fmaxf(v.w, 0.f);
            }
            if (Kb) {
                if (n < 256) {
                    *(float4*)&Cf[(size_t)m*Ndim + n] = v;
                } else {
                    __nv_bfloat162 b0 = __floats2bfloat162_rn(v.x, v.y);
                    __nv_bfloat162 b1 = __floats2bfloat162_rn(v.z, v.w);
                    __nv_bfloat16* dstb = (n < 512) ? Kb : Vb;
                    int nn = (n < 512) ? (n - 256) : (n - 512);
                    *(__nv_bfloat162*)&dstb[(size_t)m*256 + nn]     = b0;
                    *(__nv_bfloat162*)&dstb[(size_t)m*256 + nn + 2] = b1;
                }
            } else {
                if (Cf) *(float4*)&Cf[(size_t)m*Ndim + n] = v;
                if (Ch) {
                    __nv_bfloat162 h0, l0, h1, l1;
                    split2(v.x, v.y, h0, l0);
                    split2(v.z, v.w, h1, l1);
                    *(__nv_bfloat162*)&Ch[(size_t)m*Ndim + n]     = h0;
                    *(__nv_bfloat162*)&Ch[(size_t)m*Ndim + n + 2] = h1;
                    *(__nv_bfloat162*)&Cl[(size_t)m*Ndim + n]     = l0;
                    *(__nv_bfloat162*)&Cl[(size_t)m*Ndim + n + 2] = l1;
                }
            }
        }
        __syncwarp();
    }
}

// ---------------- 4) sparse masked attention (spd packed in topkidx) ----------------
__global__ void __launch_bounds__(256) attn_sparse(const float* __restrict__ emb_spd)
{
    __shared__ float sq[8][32];
    __shared__ float sp[8][104];
    __shared__ int   si[8][104];
    __shared__ float embs[8];

    const int tid = threadIdx.x, lane = tid & 31, w = tid >> 5;
    const int qt = blockIdx.x, h = blockIdx.y, b = blockIdx.z;
    const float scale = 0.17677669529663687f;

    if (tid < 7) embs[tid] = emb_spd[tid*Hh + h];
    __syncthreads();

    for (int qi = 0; qi < 4; qi++) {
        const int q = qt*32 + w*4 + qi;
        const int row = b*Nn + q;

        sq[w][lane] = g_qkv[(size_t)row*768 + h*32 + lane];
        __syncwarp();

        float sc[4];
        int   jj[4];
        float mx = -INFINITY;
        #pragma unroll
        for (int r = 0; r < 4; r++) {
            const int t = lane + r*32;
            sc[r] = -INFINITY; jj[r] = 0;
            if (t < TOPK) {
                int pk = g_topkidx[(size_t)row*104 + t];
                int j = pk & 0xFFFF;
                jj[r] = j;
                const uint4* kp = (const uint4*)&g_kb[(size_t)(b*Nn + j)*256 + h*32];
                float dot = 0.f;
                #pragma unroll
                for (int g2 = 0; g2 < 4; g2++) {
                    uint4 kv = kp[g2];
                    unsigned int kw[4] = {kv.x, kv.y, kv.z, kv.w};
                    #pragma unroll
                    for (int p4 = 0; p4 < 4; p4++) {
                        float2 f = __bfloat1622float2(*(__nv_bfloat162*)&kw[p4]);
                        dot += sq[w][g2*8 + p4*2]     * f.x
                             + sq[w][g2*8 + p4*2 + 1] * f.y;
                    }
                }
                sc[r] = dot*scale + embs[pk >> 16];
                mx = fmaxf(mx, sc[r]);
            }
        }
        #pragma unroll
        for (int o = 16; o; o >>= 1) mx = fmaxf(mx, __shfl_xor_sync(0xFFFFFFFFu, mx, o));
        float e = 0.f;
        #pragma unroll
        for (int r = 0; r < 4; r++) {
            const int t = lane + r*32;
            if (t < TOPK) {
                float p = __expf(sc[r] - mx);
                e += p;
                sp[w][t] = p;
                si[w][t] = jj[r];
            }
        }
        #pragma unroll
        for (int o = 16; o; o >>= 1) e += __shfl_xor_sync(0xFFFFFFFFu, e, o);
        __syncwarp();

        float acc = 0.f;
        #pragma unroll 6
        for (int t = 0; t < TOPK; t++) {
            int j = si[w][t];
            acc += sp[w][t] * __bfloat162float(g_vb[(size_t)(b*Nn + j)*256 + h*32 + lane]);
        }
        float v = acc / e;
        __nv_bfloat16 hh = __float2bfloat16(v);
        size_t oidx = (size_t)row*Ee + h*32 + lane;
        g_ctxh[oidx] = hh;
        g_ctxl[oidx] = __float2bfloat16(v - __bfloat162float(hh));
        __syncwarp();
    }
}

// ---------------- 5) LayerNorm (+ optional bf16 out, + optional pool score) ---------
__global__ void ln_kernel(const float* __restrict__ in, const float* __restrict__ g,
                          const float* __restrict__ be, float* __restrict__ out,
                          __nv_bfloat16* __restrict__ oh,
                          const float* __restrict__ wp, const float* __restrict__ bp,
                          float* __restrict__ scout)
{
    __shared__ float red[16];
    const int row = blockIdx.x, tid = threadIdx.x;
    float v = in[(size_t)row*Ee + tid];
    float s = v, sq = v*v;
    #pragma unroll
    for (int o = 16; o; o >>= 1) {
        s  += __shfl_xor_sync(0xFFFFFFFFu, s,  o);
        sq += __shfl_xor_sync(0xFFFFFFFFu, sq, o);
    }
    int wid = tid >> 5, lane = tid & 31;
    if (lane == 0) { red[wid] = s; red[8 + wid] = sq; }
    __syncthreads();
    if (tid == 0) {
        float ts = 0.f, tq = 0.f;
        #pragma unroll
        for (int w2 = 0; w2 < 8; w2++) { ts += red[w2]; tq += red[8 + w2]; }
        red[0] = ts; red[8] = tq;
    }
    __syncthreads();
    float mean = red[0] * (1.f/Ee);
    float var  = red[8] * (1.f/Ee) - mean*mean;
    float rstd = rsqrtf(var + 1e-5f);
    float ov = (v - mean) * rstd * g[tid] + be[tid];
    out[(size_t)row*Ee + tid] = ov;
    if (oh) oh[(size_t)row*Ee + tid] = __float2bfloat16(ov);
    if (scout) {
        float d = ov * wp[tid];
        #pragma unroll
        for (int o = 16; o; o >>= 1) d += __shfl_xor_sync(0xFFFFFFFFu, d, o);
        __syncthreads();
        if (lane == 0) red[wid] = d;
        __syncthreads();
        if (tid == 0) {
            float t2 = 0.f;
            #pragma unroll
            for (int w2 = 0; w2 < 8; w2++) t2 += red[w2];
            scout[row] = tanhf(t2 + bp[0]);
        }
    }
}

// ---------------- 6) pooling ----------------
__global__ void __launch_bounds__(256) pool2_kernel(float* __restrict__ out)
{
    __shared__ float p[512];
    __shared__ float red[8];
    __shared__ float part[8][32];
    __shared__ float Mv, Ev;
    const int b = blockIdx.x, cc = blockIdx.y;
    const int tid = threadIdx.x, lane = tid & 31, w = tid >> 5;

    float s0 = g_score[b*Nn + tid];
    float s1 = g_score[b*Nn + 256 + tid];
    float m = fmaxf(s0, s1);
    #pragma unroll
    for (int o = 16; o; o >>= 1) m = fmaxf(m, __shfl_xor_sync(0xFFFFFFFFu, m, o));
    if (lane == 0) red[w] = m;
    __syncthreads();
    if (tid == 0) {
        float mm = -INFINITY;
        #pragma unroll
        for (int i = 0; i < 8; i++) mm = fmaxf(mm, red[i]);
        Mv = mm;
    }
    __syncthreads();
    float p0 = __expf(s0 - Mv), p1 = __expf(s1 - Mv);
    p[tid] = p0; p[tid + 256] = p1;
    float e = p0 + p1;
    #pragma unroll
    for (int o = 16; o; o >>= 1) e += __shfl_xor_sync(0xFFFFFFFFu, e, o);
    if (lane == 0) red[w] = e;
    __syncthreads();
    if (tid == 0) {
        float t = 0.f;
        #pragma unroll
        for (int i = 0; i < 8; i++) t += red[i];
        Ev = t;
    }
    __syncthreads();

    const int col = cc*32 + lane;
    float acc = 0.f;
    #pragma unroll 4
    for (int i = 0; i < 64; i++) {
        int n = w*64 + i;
        acc += p[n] * g_x2[(size_t)(b*Nn + n)*Ee + col];
    }
    part[w][lane] = acc;
    __syncthreads();
    if (w == 0) {
        float a = 0.f;
        #pragma unroll
        for (int g2 = 0; g2 < 8; g2++) a += part[g2][lane];
        out[b*Ee + col] = a / Ev;
    }
}

// ---------------- launch ----------------
extern "C" void kernel_launch(void* const* d_in, const int* in_sizes, int n_in,
                              void* d_out, int out_size)
{
    const float* x       = (const float*)d_in[0];
    const float* adj     = (const float*)d_in[1];
    const float* emb_spd = (const float*)d_in[2];
    const float* w_qkv   = (const float*)d_in[3];
    const float* b_qkv   = (const float*)d_in[4];
    const float* w_out   = (const float*)d_in[5];
    const float* b_out   = (const float*)d_in[6];
    const float* w_ff1   = (const float*)d_in[7];
    const float* b_ff1   = (const float*)d_in[8];
    const float* w_ff2   = (const float*)d_in[9];
    const float* b_ff2   = (const float*)d_in[10];
    const float* g1      = (const float*)d_in[11];
    const float* beta1   = (const float*)d_in[12];
    const float* g2      = (const float*)d_in[13];
    const float* beta2   = (const float*)d_in[14];
    const float* w_pool  = (const float*)d_in[15];
    const float* b_pool  = (const float*)d_in[16];
    float* out = (float*)d_out;

    float *p_qkv, *p_y, *p_x1, *p_score;
    cudaGetSymbolAddress((void**)&p_qkv, g_qkv);
    cudaGetSymbolAddress((void**)&p_y,   g_y);
    cudaGetSymbolAddress((void**)&p_x1,  g_x1);
    cudaGetSymbolAddress((void**)&p_score, g_score);
    float* p_x2; cudaGetSymbolAddress((void**)&p_x2, g_x2);

    __nv_bfloat16 *xh, *ctxh, *ctxl, *x1h, *ffh, *ffl, *kb, *vb;
    __nv_bfloat16 *wqkvh, *wouth, *woutl, *wff1h, *wff2h, *wff2l;
    cudaGetSymbolAddress((void**)&xh, g_xh);
    cudaGetSymbolAddress((void**)&ctxh, g_ctxh); cudaGetSymbolAddress((void**)&ctxl, g_ctxl);
    cudaGetSymbolAddress((void**)&x1h, g_x1h);
    cudaGetSymbolAddress((void**)&ffh, g_ffh);   cudaGetSymbolAddress((void**)&ffl, g_ffl);
    cudaGetSymbolAddress((void**)&kb, g_kb);     cudaGetSymbolAddress((void**)&vb, g_vb);
    cudaGetSymbolAddress((void**)&wqkvh, g_wqkvh);
    cudaGetSymbolAddress((void**)&wouth, g_wouth); cudaGetSymbolAddress((void**)&woutl, g_woutl);
    cudaGetSymbolAddress((void**)&wff1h, g_wff1h);
    cudaGetSymbolAddress((void**)&wff2h, g_wff2h); cudaGetSymbolAddress((void**)&wff2l, g_wff2l);

    auto kA1 = gemm_t<128,128,2,4,1>;   // single-term: QKV, FF1 (4 bufs, smem 81920)
    auto kB3 = gemm_t<64,64,2,2,3>;     // 3-term: out-proj, FF2 (4 bufs, smem 81920)
    cudaFuncSetAttribute(kA1, cudaFuncAttributeMaxDynamicSharedMemorySize, 81920);
    cudaFuncSetAttribute(kB3, cudaFuncAttributeMaxDynamicSharedMemorySize, 81920);

    // --- fork: graph/topology branch ---
    cudaStream_t s2;
    cudaStreamCreate(&s2);
    cudaEvent_t ev0, ev1;
    cudaEventCreateWithFlags(&ev0, cudaEventDisableTiming);
    cudaEventCreateWithFlags(&ev1, cudaEventDisableTiming);

    cudaEventRecord(ev0, 0);
    cudaStreamWaitEvent(s2, ev0, 0);
    topk_kernel<<<Bb*Nn, 512, 0, s2>>>(adj);
    bfs16_kernel<<<256, 512, 0, s2>>>();
    pack_kernel<<<Bb*Nn, 128, 0, s2>>>();
    cudaEventRecord(ev1, s2);

    cvt_all<<<1792, 256>>>(x, w_qkv, w_out, w_ff1, w_ff2);
    // QKV (1-term): Q fp32, K/V bf16 direct
    kA1<<<dim3(6, 32), 256, 81920>>>(xh, nullptr, wqkvh, nullptr, b_qkv, nullptr,
                                     p_qkv, nullptr, nullptr, kb, vb, 256, 768, 0);
    cudaStreamWaitEvent(0, ev1, 0);     // join topo branch before attention
    attn_sparse<<<dim3(16, 8, 8), 256>>>(emb_spd);
    // out-proj + residual (3-term, trunk precision)
    kB3<<<dim3(4, 64), 128, 81920>>>(ctxh, ctxl, wouth, woutl, b_out, x,
                                     p_y, nullptr, nullptr, nullptr, nullptr, 256, 256, 0);
    ln_kernel<<<Mrows, 256>>>(p_y, g1, beta1, p_x1, x1h, nullptr, nullptr, nullptr);
    // FF1 + relu (1-term) -> split h/l out
    kA1<<<dim3(8, 32), 256, 81920>>>(x1h, nullptr, wff1h, nullptr, b_ff1, nullptr,
                                     nullptr, ffh, ffl, nullptr, nullptr, 256, 1024, 1);
    // FF2 + residual (3-term, trunk precision)
    kB3<<<dim3(4, 64), 128, 81920>>>(ffh, ffl, wff2h, wff2l, b_ff2, p_x1,
                                     p_y, nullptr, nullptr, nullptr, nullptr, 1024, 256, 0);
    // LN2 + fused pool score
    ln_kernel<<<Mrows, 256>>>(p_y, g2, beta2, p_x2, nullptr,
                              w_pool, b_pool, p_score);
    pool2_kernel<<<dim3(8, 8), 256>>>(out);

    cudaStreamDestroy(s2);
    cudaEventDestroy(ev0);
    cudaEventDestroy(ev1);

    (void)in_sizes; (void)n_in; (void)out_size;
}

// round 15
// speedup vs baseline: 1.0302x; 1.0302x over previous
#include <cuda_runtime.h>
#include <cuda_bf16.h>
#include <mma.h>
#include <math.h>
#include <stdint.h>

using namespace nvcuda;

#define Bb 8
#define Nn 512
#define Ee 256
#define Hh 8
#define FFd 1024
#define TOPK 102
#define Mrows (Bb*Nn)   // 4096

// ---------------- device scratch ----------------
__device__ unsigned int  g_adjbits[Bb*Nn*16];
__device__ int           g_topkidx[Bb*Nn*104];   // after pack: idx | (spd<<16)
__device__ unsigned char g_spd[Bb*Nn*Nn];
__device__ float         g_score[Mrows];
__device__ __align__(16) float g_qkv[Mrows*768];
__device__ __align__(16) float g_y  [Mrows*Ee];
__device__ __align__(16) float g_x1 [Mrows*Ee];
__device__ __align__(16) float g_x2 [Mrows*Ee];

__device__ __align__(16) __nv_bfloat16 g_kb  [Mrows*Ee];
__device__ __align__(16) __nv_bfloat16 g_vb  [Mrows*Ee];
__device__ __align__(16) __nv_bfloat16 g_xh  [Mrows*Ee];
__device__ __align__(16) __nv_bfloat16 g_ctxh[Mrows*Ee],  g_ctxl[Mrows*Ee];
__device__ __align__(16) __nv_bfloat16 g_x1h [Mrows*Ee];
__device__ __align__(16) __nv_bfloat16 g_ffh [Mrows*FFd], g_ffl [Mrows*FFd];
__device__ __align__(16) __nv_bfloat16 g_wqkvh[768*256];
__device__ __align__(16) __nv_bfloat16 g_wouth[256*256],  g_woutl[256*256];
__device__ __align__(16) __nv_bfloat16 g_wff1h[1024*256];
__device__ __align__(16) __nv_bfloat16 g_wff2h[256*1024], g_wff2l[256*1024];

// ================= helpers =================
__device__ __forceinline__ uint32_t smem_to_u32(const void* p) {
    uint32_t a;
    asm("{ .reg .u64 t; cvta.to.shared.u64 t, %1; cvt.u32.u64 %0, t; }" : "=r"(a) : "l"(p));
    return a;
}
__device__ __forceinline__ void cpasync16(uint32_t sm, const void* g) {
    asm volatile("cp.async.cg.shared.global [%0], [%1], 16;" :: "r"(sm), "l"(g) : "memory");
}
__device__ __forceinline__ void split2(float a, float b, __nv_bfloat162& h, __nv_bfloat162& l) {
    h = __floats2bfloat162_rn(a, b);
    l = __floats2bfloat162_rn(a - __bfloat162float(h.x), b - __bfloat162float(h.y));
}

// ---------------- 0) fused fp32 -> bf16 convert (lo only where needed) --------------
__global__ void cvt_all(const float* __restrict__ x, const float* __restrict__ wqkv,
                        const float* __restrict__ wout, const float* __restrict__ wff1,
                        const float* __restrict__ wff2)
{
    int gid = blockIdx.x*256 + threadIdx.x;       // float4 index, total 458752
    const float* in; __nv_bfloat16 *hi, *lo = nullptr; int off;
    if      (gid < 262144) { in = x;    hi = g_xh;    off = gid; }
    else if (gid < 311296) { in = wqkv; hi = g_wqkvh; off = gid - 262144; }
    else if (gid < 327680) { in = wout; hi = g_wouth; lo = g_woutl; off = gid - 311296; }
    else if (gid < 393216) { in = wff1; hi = g_wff1h; off = gid - 327680; }
    else                   { in = wff2; hi = g_wff2h; lo = g_wff2l; off = gid - 393216; }
    float4 v = ((const float4*)in)[off];
    __nv_bfloat162 h0, l0, h1, l1;
    split2(v.x, v.y, h0, l0);
    split2(v.z, v.w, h1, l1);
    int i = off*4;
    *(__nv_bfloat162*)(hi + i)     = h0;
    *(__nv_bfloat162*)(hi + i + 2) = h1;
    if (lo) {
        *(__nv_bfloat162*)(lo + i)     = l0;
        *(__nv_bfloat162*)(lo + i + 2) = l1;
    }
}

// ---------------- 1) top-k (512 threads) ----------------------------------------------
__global__ void __launch_bounds__(512) topk_kernel(const float* __restrict__ adj)
{
    __shared__ unsigned long long keys[512];
    __shared__ unsigned int bw[16];
    const int row = blockIdx.x;
    const int tid = threadIdx.x;

    {
        unsigned int bits = __float_as_uint(adj[(size_t)row*512 + tid]);
        unsigned int ord  = bits ^ ((bits & 0x80000000u) ? 0xFFFFFFFFu : 0x80000000u);
        keys[tid] = ((unsigned long long)ord << 32) | (unsigned long long)(511 - tid);
    }
    if (tid < 16) bw[tid] = 0u;
    __syncthreads();

    for (int k = 2; k <= 512; k <<= 1) {
        for (int jj = k >> 1; jj > 0; jj >>= 1) {
            int i = tid;
            int ixj = i ^ jj;
            if (ixj > i) {
                unsigned long long a = keys[i], c = keys[ixj];
                bool up = ((i & k) == 0);
                if ((a > c) == up) { keys[i] = c; keys[ixj] = a; }
            }
            __syncthreads();
        }
    }
    if (tid < TOPK) {
        int j = 511 - (int)(keys[410 + tid] & 0xFFFFFFFFull);
        atomicOr(&bw[j >> 5], 1u << (j & 31));
        g_topkidx[(size_t)row*104 + tid] = j;
    }
    __syncthreads();
    if (tid < 16) g_adjbits[row*16 + tid] = bw[tid];
}

// ---------------- 2) BFS: 16 warps = 16 independent sources, smem adjacency ---------
__global__ void __launch_bounds__(512) bfs16_kernel()
{
    __shared__ unsigned int adjs[512*17];
    const int tid = threadIdx.x, lane = tid & 31, w = tid >> 5;
    const int blk = blockIdx.x;                 // 0..255
    const int b = blk >> 5;
    const int s0 = (blk & 31) << 4;

    #pragma unroll
    for (int k = 0; k < 16; k++)
        adjs[tid*17 + k] = g_adjbits[((size_t)(b*Nn) + tid)*16 + k];
    __syncthreads();

    const int src = s0 + w;
    const size_t spdbase = (size_t)(b*Nn + src) * Nn;

    for (int i = lane; i < 128; i += 32)
        ((unsigned int*)(g_spd + spdbase))[i] = 0u;
    __syncwarp();
    if (lane == 0) g_spd[spdbase + src] = 1;

    unsigned int visw = 0u, frow = 0u;
    if (lane < 16) {
        frow = (lane == (src >> 5)) ? (1u << (src & 31)) : 0u;
        visw = frow;
    }

    for (int level = 1; level <= 10; level++) {
        unsigned int acc[16];
        #pragma unroll
        for (int k = 0; k < 16; k++) acc[k] = 0u;

        #pragma unroll 1
        for (int wd = 0; wd < 16; wd++) {
            unsigned int bits = __shfl_sync(0xFFFFFFFFu, frow, wd);
            if ((bits >> lane) & 1u) {
                const unsigned int* row = &adjs[(wd*32 + lane)*17];
                #pragma unroll
                for (int k = 0; k < 16; k++) acc[k] |= row[k];
            }
        }
        unsigned int nv = 0u;
        #pragma unroll
        for (int k = 0; k < 16; k++) {
            unsigned int full = __reduce_or_sync(0xFFFFFFFFu, acc[k]);
            if (lane == k) nv = full & ~visw;
        }
        if (lane < 16) { visw |= nv; frow = nv; } else frow = 0u;

        unsigned int any = __reduce_or_sync(0xFFFFFFFFu, (lane < 16) ? nv : 0u);
        if (!any) break;

        unsigned char dval = (unsigned char)((level + 1 < 6) ? level + 1 : 6);
        #pragma unroll 1
        for (int wd = 0; wd < 16; wd++) {
            unsigned int bits = __shfl_sync(0xFFFFFFFFu, frow, wd);
            if ((bits >> lane) & 1u)
                g_spd[spdbase + wd*32 + lane] = dval;
        }
    }
}

// ---------------- 2b) pack spd into topkidx -------------------------------------------
__global__ void __launch_bounds__(128) pack_kernel()
{
    const int row = blockIdx.x;           // 0..4095
    const int t = threadIdx.x;
    if (t < TOPK) {
        int j = g_topkidx[(size_t)row*104 + t];
        int spd = g_spd[(size_t)row*Nn + j];
        g_topkidx[(size_t)row*104 + t] = j | (spd << 16);
    }
}

// ---------------- 3) pipelined bf16 wmma GEMM: 4 buffers, 1 sync/chunk ---------------
template<int BM, int BN, int WR, int WC, int TERMS>
__global__ void __launch_bounds__(WR*WC*32, 2) gemm_t(
    const __nv_bfloat16* __restrict__ Ah, const __nv_bfloat16* __restrict__ Al,
    const __nv_bfloat16* __restrict__ Wh, const __nv_bfloat16* __restrict__ Wl,
    const float* __restrict__ bias, const float* __restrict__ res,
    float* __restrict__ Cf, __nv_bfloat16* __restrict__ Ch, __nv_bfloat16* __restrict__ Cl,
    __nv_bfloat16* __restrict__ Kb, __nv_bfloat16* __restrict__ Vb,
    int K, int Ndim, int relu)
{
    constexpr int WARPS = WR*WC, THREADS = WARPS*32;
    constexpr int WM = BM/WR, WN = BN/WC, FR = WM/16, FC = WN/16;
    static_assert(WN == 32, "epilogue assumes WN==32");
    constexpr int NM = (TERMS == 3) ? 2 : 1;
    constexpr int AROWS = BM*40;
    constexpr int WROWS = BN*40;
    constexpr int BUFB = (NM*AROWS + NM*WROWS)*2;
    constexpr int SLOTS = (NM*BM + NM*BN)*2;

    extern __shared__ __align__(128) char s[];
    const uint32_t sb = smem_to_u32(s);
    const int tid = threadIdx.x, wid = tid >> 5, lane = tid & 31;
    const int m0 = blockIdx.y * BM, n0 = blockIdx.x * BN;
    const int wr = wid / WC, wc = wid % WC;

    wmma::fragment<wmma::accumulator,16,16,16,float> acc[FR][FC];
    #pragma unroll
    for (int r = 0; r < FR; r++)
        #pragma unroll
        for (int t = 0; t < FC; t++) wmma::fill_fragment(acc[r][t], 0.f);

    auto stage = [&](int c, int buf) {
        const int kk = c * 32;
        #pragma unroll
        for (int sl = tid; sl < SLOTS; sl += THREADS) {
            int half = sl & 1, rowid = sl >> 1;
            const __nv_bfloat16* src; uint32_t dst;
            if (rowid < BM) {
                src = Ah + (size_t)(m0 + rowid)*K;
                dst = sb + buf*BUFB + rowid*80;
            } else if (TERMS == 3 && rowid < 2*BM) {
                int r2 = rowid - BM;
                src = Al + (size_t)(m0 + r2)*K;
                dst = sb + buf*BUFB + AROWS*2 + r2*80;
            } else if (rowid < NM*BM + BN) {
                int r2 = rowid - NM*BM;
                src = Wh + (size_t)(n0 + r2)*K;
                dst = sb + buf*BUFB + NM*AROWS*2 + r2*80;
            } else {
                int r2 = rowid - NM*BM - BN;
                src = Wl + (size_t)(n0 + r2)*K;
                dst = sb + buf*BUFB + NM*AROWS*2 + WROWS*2 + r2*80;
            }
            cpasync16(dst + half*32,      src + kk + half*16);
            cpasync16(dst + half*32 + 16, src + kk + half*16 + 8);
        }
        asm volatile("cp.async.commit_group;" ::: "memory");
    };

    const int nc = K >> 5;
    stage(0, 0);
    stage(1, 1);

    for (int c = 0; c < nc; c++) {
        if (c + 2 < nc) stage(c + 2, (c + 2) & 3);
        if (c + 2 < nc)       asm volatile("cp.async.wait_group 2;" ::: "memory");
        else if (c + 1 < nc)  asm volatile("cp.async.wait_group 1;" ::: "memory");
        else                  asm volatile("cp.async.wait_group 0;" ::: "memory");
        __syncthreads();

        const __nv_bfloat16* sAh = (const __nv_bfloat16*)(s + (c & 3)*BUFB);
        const __nv_bfloat16* sAl = sAh + AROWS;
        const __nv_bfloat16* sWh = sAh + NM*AROWS;
        const __nv_bfloat16* sWl = sWh + WROWS;

        #pragma unroll
        for (int ks = 0; ks < 2; ks++) {
            wmma::fragment<wmma::matrix_a,16,16,16,__nv_bfloat16,wmma::row_major> af[FR];
            wmma::fragment<wmma::matrix_b,16,16,16,__nv_bfloat16,wmma::col_major> bf_[FC];
            // term 1: Ah * Wh
            #pragma unroll
            for (int r = 0; r < FR; r++)
                wmma::load_matrix_sync(af[r], sAh + (wr*WM + r*16)*40 + ks*16, 40);
            #pragma unroll
            for (int t = 0; t < FC; t++)
                wmma::load_matrix_sync(bf_[t], sWh + (wc*WN + t*16)*40 + ks*16, 40);
            #pragma unroll
            for (int r = 0; r < FR; r++)
                #pragma unroll
                for (int t = 0; t < FC; t++) wmma::mma_sync(acc[r][t], af[r], bf_[t], acc[r][t]);
            if (TERMS == 3) {
                // term 2: Ah * Wl
                #pragma unroll
                for (int t = 0; t < FC; t++)
                    wmma::load_matrix_sync(bf_[t], sWl + (wc*WN + t*16)*40 + ks*16, 40);
                #pragma unroll
                for (int r = 0; r < FR; r++)
                    #pragma unroll
                    for (int t = 0; t < FC; t++) wmma::mma_sync(acc[r][t], af[r], bf_[t], acc[r][t]);
                // term 3: Al * Wh
                #pragma unroll
                for (int r = 0; r < FR; r++)
                    wmma::load_matrix_sync(af[r], sAl + (wr*WM + r*16)*40 + ks*16, 40);
                #pragma unroll
                for (int t = 0; t < FC; t++)
                    wmma::load_matrix_sync(bf_[t], sWh + (wc*WN + t*16)*40 + ks*16, 40);
                #pragma unroll
                for (int r = 0; r < FR; r++)
                    #pragma unroll
                    for (int t = 0; t < FC; t++) wmma::mma_sync(acc[r][t], af[r], bf_[t], acc[r][t]);
            }
        }
    }
    __syncthreads();

    // epilogue
    float* ep = (float*)s + wid*16*40;
    const int rr = lane & 15, hf = lane >> 4;
    #pragma unroll
    for (int rt = 0; rt < FR; rt++) {
        wmma::store_matrix_sync(ep,      acc[rt][0], 40, wmma::mem_row_major);
        wmma::store_matrix_sync(ep + 16, acc[rt][1], 40, wmma::mem_row_major);
        __syncwarp();
        const int m = m0 + wr*WM + rt*16 + rr;
        #pragma unroll
        for (int q = 0; q < 4; q++) {
            const int n = n0 + wc*WN + hf*16 + q*4;
            float4 v = *(float4*)&ep[rr*40 + hf*16 + q*4];
            float4 bv = *(const float4*)&bias[n];
            v.x += bv.x; v.y += bv.y; v.z += bv.z; v.w += bv.w;
            if (res) {
                float4 rv = *(const float4*)&res[(size_t)m*Ndim + n];
                v.x += rv.x; v.y += rv.y; v.z += rv.z; v.w += rv.w;
            }
            if (relu) {
                v.x = fmaxf(v.x, 0.f); v.y = fmaxf(v.y, 0.f);
                v.z = fmaxf(v.z, 0.f); v.w = fmaxf(v.w, 0.f);
            }
            if (Kb) {
                if (n < 256) {
                    *(float4*)&Cf[(size_t)m*Ndim + n] = v;
                } else {
                    __nv_bfloat162 b0 = __floats2bfloat162_rn(v.x, v.y);
                    __nv_bfloat162 b1 = __floats2bfloat162_rn(v.z, v.w);
                    __nv_bfloat16* dstb = (n < 512) ? Kb : Vb;
                    int nn = (n < 512) ? (n - 256) : (n - 512);
                    *(__nv_bfloat162*)&dstb[(size_t)m*256 + nn]     = b0;
                    *(__nv_bfloat162*)&dstb[(size_t)m*256 + nn + 2] = b1;
                }
            } else {
                if (Cf) *(float4*)&Cf[(size_t)m*Ndim + n] = v;
                if (Ch) {
                    __nv_bfloat162 h0, l0, h1, l1;
                    split2(v.x, v.y, h0, l0);
                    split2(v.z, v.w, h1, l1);
                    *(__nv_bfloat162*)&Ch[(size_t)m*Ndim + n]     = h0;
                    *(__nv_bfloat162*)&Ch[(size_t)m*Ndim + n + 2] = h1;
                    *(__nv_bfloat162*)&Cl[(size_t)m*Ndim + n]     = l0;
                    *(__nv_bfloat162*)&Cl[(size_t)m*Ndim + n + 2] = l1;
                }
            }
        }
        __syncwarp();
    }
}

// ---------------- 4) sparse attention: V tile in smem, 16 queries/warp --------------
__global__ void __launch_bounds__(256) attn_sparse(const float* __restrict__ emb_spd)
{
    __shared__ __nv_bfloat16 vs[512*32];      // V tile for (b,h): 32 KB
    __shared__ float sq[8][32];
    __shared__ float sp[8][104];
    __shared__ int   si[8][104];
    __shared__ float embs[8];

    const int tid = threadIdx.x, lane = tid & 31, w = tid >> 5;
    const int qc = blockIdx.x, h = blockIdx.y, b = blockIdx.z;
    const float scale = 0.17677669529663687f;

    // cooperative V tile load (coalesced 64B segments)
    #pragma unroll
    for (int i = tid; i < 2048; i += 256) {
        int row = i >> 2, seg = i & 3;
        ((uint4*)vs)[i] = *(const uint4*)&g_vb[(size_t)(b*Nn + row)*256 + h*32 + seg*8];
    }
    if (tid < 7) embs[tid] = emb_spd[tid*Hh + h];
    __syncthreads();

    for (int qi = 0; qi < 16; qi++) {
        const int q = qc*128 + w*16 + qi;
        const int row = b*Nn + q;

        sq[w][lane] = g_qkv[(size_t)row*768 + h*32 + lane];
        __syncwarp();

        float sc[4];
        int   jj[4];
        float mx = -INFINITY;
        #pragma unroll
        for (int r = 0; r < 4; r++) {
            const int t = lane + r*32;
            sc[r] = -INFINITY; jj[r] = 0;
            if (t < TOPK) {
                int pk = g_topkidx[(size_t)row*104 + t];
                int j = pk & 0xFFFF;
                jj[r] = j;
                const uint4* kp = (const uint4*)&g_kb[(size_t)(b*Nn + j)*256 + h*32];
                float dot = 0.f;
                #pragma unroll
                for (int g2 = 0; g2 < 4; g2++) {
                    uint4 kv = kp[g2];
                    unsigned int kw[4] = {kv.x, kv.y, kv.z, kv.w};
                    #pragma unroll
                    for (int p4 = 0; p4 < 4; p4++) {
                        float2 f = __bfloat1622float2(*(__nv_bfloat162*)&kw[p4]);
                        dot += sq[w][g2*8 + p4*2]     * f.x
                             + sq[w][g2*8 + p4*2 + 1] * f.y;
                    }
                }
                sc[r] = dot*scale + embs[pk >> 16];
                mx = fmaxf(mx, sc[r]);
            }
        }
        #pragma unroll
        for (int o = 16; o; o >>= 1) mx = fmaxf(mx, __shfl_xor_sync(0xFFFFFFFFu, mx, o));
        float e = 0.f;
        #pragma unroll
        for (int r = 0; r < 4; r++) {
            const int t = lane + r*32;
            if (t < TOPK) {
                float p = __expf(sc[r] - mx);
                e += p;
                sp[w][t] = p;
                si[w][t] = jj[r];
            }
        }
        #pragma unroll
        for (int o = 16; o; o >>= 1) e += __shfl_xor_sync(0xFFFFFFFFu, e, o);
        __syncwarp();

        float acc = 0.f;
        #pragma unroll 6
        for (int t = 0; t < TOPK; t++) {
            int j = si[w][t];
            acc += sp[w][t] * __bfloat162float(vs[j*32 + lane]);
        }
        float v = acc / e;
        __nv_bfloat16 hh = __float2bfloat16(v);
        size_t oidx = (size_t)row*Ee + h*32 + lane;
        g_ctxh[oidx] = hh;
        g_ctxl[oidx] = __float2bfloat16(v - __bfloat162float(hh));
        __syncwarp();
    }
}

// ---------------- 5) LayerNorm (+ optional bf16 out, + optional pool score) ---------
__global__ void ln_kernel(const float* __restrict__ in, const float* __restrict__ g,
                          const float* __restrict__ be, float* __restrict__ out,
                          __nv_bfloat16* __restrict__ oh,
                          const float* __restrict__ wp, const float* __restrict__ bp,
                          float* __restrict__ scout)
{
    __shared__ float red[16];
    const int row = blockIdx.x, tid = threadIdx.x;
    float v = in[(size_t)row*Ee + tid];
    float s = v, sq = v*v;
    #pragma unroll
    for (int o = 16; o; o >>= 1) {
        s  += __shfl_xor_sync(0xFFFFFFFFu, s,  o);
        sq += __shfl_xor_sync(0xFFFFFFFFu, sq, o);
    }
    int wid = tid >> 5, lane = tid & 31;
    if (lane == 0) { red[wid] = s; red[8 + wid] = sq; }
    __syncthreads();
    if (tid == 0) {
        float ts = 0.f, tq = 0.f;
        #pragma unroll
        for (int w2 = 0; w2 < 8; w2++) { ts += red[w2]; tq += red[8 + w2]; }
        red[0] = ts; red[8] = tq;
    }
    __syncthreads();
    float mean = red[0] * (1.f/Ee);
    float var  = red[8] * (1.f/Ee) - mean*mean;
    float rstd = rsqrtf(var + 1e-5f);
    float ov = (v - mean) * rstd * g[tid] + be[tid];
    out[(size_t)row*Ee + tid] = ov;
    if (oh) oh[(size_t)row*Ee + tid] = __float2bfloat16(ov);
    if (scout) {
        float d = ov * wp[tid];
        #pragma unroll
        for (int o = 16; o; o >>= 1) d += __shfl_xor_sync(0xFFFFFFFFu, d, o);
        __syncthreads();
        if (lane == 0) red[wid] = d;
        __syncthreads();
        if (tid == 0) {
            float t2 = 0.f;
            #pragma unroll
            for (int w2 = 0; w2 < 8; w2++) t2 += red[w2];
            scout[row] = tanhf(t2 + bp[0]);
        }
    }
}

// ---------------- 6) pooling ----------------
__global__ void __launch_bounds__(256) pool2_kernel(float* __restrict__ out)
{
    __shared__ float p[512];
    __shared__ float red[8];
    __shared__ float part[8][32];
    __shared__ float Mv, Ev;
    const int b = blockIdx.x, cc = blockIdx.y;
    const int tid = threadIdx.x, lane = tid & 31, w = tid >> 5;

    float s0 = g_score[b*Nn + tid];
    float s1 = g_score[b*Nn + 256 + tid];
    float m = fmaxf(s0, s1);
    #pragma unroll
    for (int o = 16; o; o >>= 1) m = fmaxf(m, __shfl_xor_sync(0xFFFFFFFFu, m, o));
    if (lane == 0) red[w] = m;
    __syncthreads();
    if (tid == 0) {
        float mm = -INFINITY;
        #pragma unroll
        for (int i = 0; i < 8; i++) mm = fmaxf(mm, red[i]);
        Mv = mm;
    }
    __syncthreads();
    float p0 = __expf(s0 - Mv), p1 = __expf(s1 - Mv);
    p[tid] = p0; p[tid + 256] = p1;
    float e = p0 + p1;
    #pragma unroll
    for (int o = 16; o; o >>= 1) e += __shfl_xor_sync(0xFFFFFFFFu, e, o);
    if (lane == 0) red[w] = e;
    __syncthreads();
    if (tid == 0) {
        float t = 0.f;
        #pragma unroll
        for (int i = 0; i < 8; i++) t += red[i];
        Ev = t;
    }
    __syncthreads();

    const int col = cc*32 + lane;
    float acc = 0.f;
    #pragma unroll 4
    for (int i = 0; i < 64; i++) {
        int n = w*64 + i;
        acc += p[n] * g_x2[(size_t)(b*Nn + n)*Ee + col];
    }
    part[w][lane] = acc;
    __syncthreads();
    if (w == 0) {
        float a = 0.f;
        #pragma unroll
        for (int g2 = 0; g2 < 8; g2++) a += part[g2][lane];
        out[b*Ee + col] = a / Ev;
    }
}

// ---------------- launch ----------------
extern "C" void kernel_launch(void* const* d_in, const int* in_sizes, int n_in,
                              void* d_out, int out_size)
{
    const float* x       = (const float*)d_in[0];
    const float* adj     = (const float*)d_in[1];
    const float* emb_spd = (const float*)d_in[2];
    const float* w_qkv   = (const float*)d_in[3];
    const float* b_qkv   = (const float*)d_in[4];
    const float* w_out   = (const float*)d_in[5];
    const float* b_out   = (const float*)d_in[6];
    const float* w_ff1   = (const float*)d_in[7];
    const float* b_ff1   = (const float*)d_in[8];
    const float* w_ff2   = (const float*)d_in[9];
    const float* b_ff2   = (const float*)d_in[10];
    const float* g1      = (const float*)d_in[11];
    const float* beta1   = (const float*)d_in[12];
    const float* g2      = (const float*)d_in[13];
    const float* beta2   = (const float*)d_in[14];
    const float* w_pool  = (const float*)d_in[15];
    const float* b_pool  = (const float*)d_in[16];
    float* out = (float*)d_out;

    float *p_qkv, *p_y, *p_x1, *p_score;
    cudaGetSymbolAddress((void**)&p_qkv, g_qkv);
    cudaGetSymbolAddress((void**)&p_y,   g_y);
    cudaGetSymbolAddress((void**)&p_x1,  g_x1);
    cudaGetSymbolAddress((void**)&p_score, g_score);
    float* p_x2; cudaGetSymbolAddress((void**)&p_x2, g_x2);

    __nv_bfloat16 *xh, *ctxh, *ctxl, *x1h, *ffh, *ffl, *kb, *vb;
    __nv_bfloat16 *wqkvh, *wouth, *woutl, *wff1h, *wff2h, *wff2l;
    cudaGetSymbolAddress((void**)&xh, g_xh);
    cudaGetSymbolAddress((void**)&ctxh, g_ctxh); cudaGetSymbolAddress((void**)&ctxl, g_ctxl);
    cudaGetSymbolAddress((void**)&x1h, g_x1h);
    cudaGetSymbolAddress((void**)&ffh, g_ffh);   cudaGetSymbolAddress((void**)&ffl, g_ffl);
    cudaGetSymbolAddress((void**)&kb, g_kb);     cudaGetSymbolAddress((void**)&vb, g_vb);
    cudaGetSymbolAddress((void**)&wqkvh, g_wqkvh);
    cudaGetSymbolAddress((void**)&wouth, g_wouth); cudaGetSymbolAddress((void**)&woutl, g_woutl);
    cudaGetSymbolAddress((void**)&wff1h, g_wff1h);
    cudaGetSymbolAddress((void**)&wff2h, g_wff2h); cudaGetSymbolAddress((void**)&wff2l, g_wff2l);

    auto kA1 = gemm_t<128,128,2,4,1>;   // single-term: QKV, FF1 (4 bufs, smem 81920)
    auto kB3 = gemm_t<64,64,2,2,3>;     // 3-term: out-proj, FF2 (4 bufs, smem 81920)
    cudaFuncSetAttribute(kA1, cudaFuncAttributeMaxDynamicSharedMemorySize, 81920);
    cudaFuncSetAttribute(kB3, cudaFuncAttributeMaxDynamicSharedMemorySize, 81920);

    // --- fork: graph/topology branch ---
    cudaStream_t s2;
    cudaStreamCreate(&s2);
    cudaEvent_t ev0, ev1;
    cudaEventCreateWithFlags(&ev0, cudaEventDisableTiming);
    cudaEventCreateWithFlags(&ev1, cudaEventDisableTiming);

    cudaEventRecord(ev0, 0);
    cudaStreamWaitEvent(s2, ev0, 0);
    topk_kernel<<<Bb*Nn, 512, 0, s2>>>(adj);
    bfs16_kernel<<<256, 512, 0, s2>>>();
    pack_kernel<<<Bb*Nn, 128, 0, s2>>>();
    cudaEventRecord(ev1, s2);

    cvt_all<<<1792, 256>>>(x, w_qkv, w_out, w_ff1, w_ff2);
    // QKV (1-term): Q fp32, K/V bf16 direct
    kA1<<<dim3(6, 32), 256, 81920>>>(xh, nullptr, wqkvh, nullptr, b_qkv, nullptr,
                                     p_qkv, nullptr, nullptr, kb, vb, 256, 768, 0);
    cudaStreamWaitEvent(0, ev1, 0);     // join topo branch before attention
    attn_sparse<<<dim3(4, 8, 8), 256>>>(emb_spd);
    // out-proj + residual (3-term, trunk precision)
    kB3<<<dim3(4, 64), 128, 81920>>>(ctxh, ctxl, wouth, woutl, b_out, x,
                                     p_y, nullptr, nullptr, nullptr, nullptr, 256, 256, 0);
    ln_kernel<<<Mrows, 256>>>(p_y, g1, beta1, p_x1, x1h, nullptr, nullptr, nullptr);
    // FF1 + relu (1-term) -> split h/l out
    kA1<<<dim3(8, 32), 256, 81920>>>(x1h, nullptr, wff1h, nullptr, b_ff1, nullptr,
                                     nullptr, ffh, ffl, nullptr, nullptr, 256, 1024, 1);
    // FF2 + residual (3-term, trunk precision)
    kB3<<<dim3(4, 64), 128, 81920>>>(ffh, ffl, wff2h, wff2l, b_ff2, p_x1,
                                     p_y, nullptr, nullptr, nullptr, nullptr, 1024, 256, 0);
    // LN2 + fused pool score
    ln_kernel<<<Mrows, 256>>>(p_y, g2, beta2, p_x2, nullptr,
                              w_pool, b_pool, p_score);
    pool2_kernel<<<dim3(8, 8), 256>>>(out);

    cudaStreamDestroy(s2);
    cudaEventDestroy(ev0);
    cudaEventDestroy(ev1);

    (void)in_sizes; (void)n_in; (void)out_size;
}

// round 16
// speedup vs baseline: 1.1978x; 1.1626x over previous
#include <cuda_runtime.h>
#include <cuda_bf16.h>
#include <mma.h>
#include <math.h>
#include <stdint.h>

using namespace nvcuda;

#define Bb 8
#define Nn 512
#define Ee 256
#define Hh 8
#define FFd 1024
#define TOPK 102
#define Mrows (Bb*Nn)   // 4096

// ---------------- device scratch ----------------
__device__ unsigned int  g_adjbits[Bb*Nn*16];
__device__ int           g_topkidx[Bb*Nn*104];   // packed: idx | (spd<<16)
__device__ unsigned char g_spd[Bb*Nn*Nn];
__device__ float         g_score[Mrows];
__device__ __align__(16) float g_qkv[Mrows*768];
__device__ __align__(16) float g_y  [Mrows*Ee];
__device__ __align__(16) float g_x1 [Mrows*Ee];
__device__ __align__(16) float g_x2 [Mrows*Ee];

__device__ __align__(16) __nv_bfloat16 g_kb  [Mrows*Ee];
__device__ __align__(16) __nv_bfloat16 g_vb  [Mrows*Ee];
__device__ __align__(16) __nv_bfloat16 g_xh  [Mrows*Ee];
__device__ __align__(16) __nv_bfloat16 g_ctxh[Mrows*Ee],  g_ctxl[Mrows*Ee];
__device__ __align__(16) __nv_bfloat16 g_x1h [Mrows*Ee];
__device__ __align__(16) __nv_bfloat16 g_ffh [Mrows*FFd], g_ffl [Mrows*FFd];
__device__ __align__(16) __nv_bfloat16 g_wqkvh[768*256];
__device__ __align__(16) __nv_bfloat16 g_wouth[256*256],  g_woutl[256*256];
__device__ __align__(16) __nv_bfloat16 g_wff1h[1024*256];
__device__ __align__(16) __nv_bfloat16 g_wff2h[256*1024], g_wff2l[256*1024];

// ================= helpers =================
__device__ __forceinline__ uint32_t smem_to_u32(const void* p) {
    uint32_t a;
    asm("{ .reg .u64 t; cvta.to.shared.u64 t, %1; cvt.u32.u64 %0, t; }" : "=r"(a) : "l"(p));
    return a;
}
__device__ __forceinline__ void cpasync16(uint32_t sm, const void* g) {
    asm volatile("cp.async.cg.shared.global [%0], [%1], 16;" :: "r"(sm), "l"(g) : "memory");
}
__device__ __forceinline__ void split2(float a, float b, __nv_bfloat162& h, __nv_bfloat162& l) {
    h = __floats2bfloat162_rn(a, b);
    l = __floats2bfloat162_rn(a - __bfloat162float(h.x), b - __bfloat162float(h.y));
}

// ---------------- 0) fused fp32 -> bf16 convert (lo only where needed) --------------
__global__ void cvt_all(const float* __restrict__ x, const float* __restrict__ wqkv,
                        const float* __restrict__ wout, const float* __restrict__ wff1,
                        const float* __restrict__ wff2)
{
    int gid = blockIdx.x*256 + threadIdx.x;       // float4 index, total 458752
    const float* in; __nv_bfloat16 *hi, *lo = nullptr; int off;
    if      (gid < 262144) { in = x;    hi = g_xh;    off = gid; }
    else if (gid < 311296) { in = wqkv; hi = g_wqkvh; off = gid - 262144; }
    else if (gid < 327680) { in = wout; hi = g_wouth; lo = g_woutl; off = gid - 311296; }
    else if (gid < 393216) { in = wff1; hi = g_wff1h; off = gid - 327680; }
    else                   { in = wff2; hi = g_wff2h; lo = g_wff2l; off = gid - 393216; }
    float4 v = ((const float4*)in)[off];
    __nv_bfloat162 h0, l0, h1, l1;
    split2(v.x, v.y, h0, l0);
    split2(v.z, v.w, h1, l1);
    int i = off*4;
    *(__nv_bfloat162*)(hi + i)     = h0;
    *(__nv_bfloat162*)(hi + i + 2) = h1;
    if (lo) {
        *(__nv_bfloat162*)(lo + i)     = l0;
        *(__nv_bfloat162*)(lo + i + 2) = l1;
    }
}

// ---------------- 1) top-k (512 threads) ----------------------------------------------
__global__ void __launch_bounds__(512) topk_kernel(const float* __restrict__ adj)
{
    __shared__ unsigned long long keys[512];
    __shared__ unsigned int bw[16];
    const int row = blockIdx.x;
    const int tid = threadIdx.x;

    {
        unsigned int bits = __float_as_uint(adj[(size_t)row*512 + tid]);
        unsigned int ord  = bits ^ ((bits & 0x80000000u) ? 0xFFFFFFFFu : 0x80000000u);
        keys[tid] = ((unsigned long long)ord << 32) | (unsigned long long)(511 - tid);
    }
    if (tid < 16) bw[tid] = 0u;
    __syncthreads();

    for (int k = 2; k <= 512; k <<= 1) {
        for (int jj = k >> 1; jj > 0; jj >>= 1) {
            int i = tid;
            int ixj = i ^ jj;
            if (ixj > i) {
                unsigned long long a = keys[i], c = keys[ixj];
                bool up = ((i & k) == 0);
                if ((a > c) == up) { keys[i] = c; keys[ixj] = a; }
            }
            __syncthreads();
        }
    }
    if (tid < TOPK) {
        int j = 511 - (int)(keys[410 + tid] & 0xFFFFFFFFull);
        atomicOr(&bw[j >> 5], 1u << (j & 31));
        g_topkidx[(size_t)row*104 + tid] = j;
    }
    __syncthreads();
    if (tid < 16) g_adjbits[row*16 + tid] = bw[tid];
}

// ---------------- 2) BFS + fused spd-pack: 16 warps = 16 sources --------------------
__global__ void __launch_bounds__(512) bfs16_kernel()
{
    __shared__ unsigned int adjs[512*17];
    const int tid = threadIdx.x, lane = tid & 31, w = tid >> 5;
    const int blk = blockIdx.x;                 // 0..255
    const int b = blk >> 5;
    const int s0 = (blk & 31) << 4;

    #pragma unroll
    for (int k = 0; k < 16; k++)
        adjs[tid*17 + k] = g_adjbits[((size_t)(b*Nn) + tid)*16 + k];
    __syncthreads();

    const int src = s0 + w;
    const size_t spdbase = (size_t)(b*Nn + src) * Nn;

    for (int i = lane; i < 128; i += 32)
        ((unsigned int*)(g_spd + spdbase))[i] = 0u;
    __syncwarp();
    if (lane == 0) g_spd[spdbase + src] = 1;

    unsigned int visw = 0u, frow = 0u;
    if (lane < 16) {
        frow = (lane == (src >> 5)) ? (1u << (src & 31)) : 0u;
        visw = frow;
    }

    for (int level = 1; level <= 10; level++) {
        unsigned int acc[16];
        #pragma unroll
        for (int k = 0; k < 16; k++) acc[k] = 0u;

        #pragma unroll 1
        for (int wd = 0; wd < 16; wd++) {
            unsigned int bits = __shfl_sync(0xFFFFFFFFu, frow, wd);
            if ((bits >> lane) & 1u) {
                const unsigned int* row = &adjs[(wd*32 + lane)*17];
                #pragma unroll
                for (int k = 0; k < 16; k++) acc[k] |= row[k];
            }
        }
        unsigned int nv = 0u;
        #pragma unroll
        for (int k = 0; k < 16; k++) {
            unsigned int full = __reduce_or_sync(0xFFFFFFFFu, acc[k]);
            if (lane == k) nv = full & ~visw;
        }
        if (lane < 16) { visw |= nv; frow = nv; } else frow = 0u;

        unsigned int any = __reduce_or_sync(0xFFFFFFFFu, (lane < 16) ? nv : 0u);
        if (!any) break;

        unsigned char dval = (unsigned char)((level + 1 < 6) ? level + 1 : 6);
        #pragma unroll 1
        for (int wd = 0; wd < 16; wd++) {
            unsigned int bits = __shfl_sync(0xFFFFFFFFu, frow, wd);
            if ((bits >> lane) & 1u)
                g_spd[spdbase + wd*32 + lane] = dval;
        }
    }
    __syncwarp();

    // fused pack: spd index into topkidx bits [16:24) for this source row
    const size_t tbase = (size_t)(b*Nn + src) * 104;
    for (int t = lane; t < TOPK; t += 32) {
        int j = g_topkidx[tbase + t];
        int spd = g_spd[spdbase + j];
        g_topkidx[tbase + t] = j | (spd << 16);
    }
}

// ---------------- 3) pipelined bf16 wmma GEMM: 4 buffers, 1 sync/chunk ---------------
template<int BM, int BN, int WR, int WC, int TERMS>
__global__ void __launch_bounds__(WR*WC*32, 2) gemm_t(
    const __nv_bfloat16* __restrict__ Ah, const __nv_bfloat16* __restrict__ Al,
    const __nv_bfloat16* __restrict__ Wh, const __nv_bfloat16* __restrict__ Wl,
    const float* __restrict__ bias, const float* __restrict__ res,
    float* __restrict__ Cf, __nv_bfloat16* __restrict__ Ch, __nv_bfloat16* __restrict__ Cl,
    __nv_bfloat16* __restrict__ Kb, __nv_bfloat16* __restrict__ Vb,
    int K, int Ndim, int relu)
{
    constexpr int WARPS = WR*WC, THREADS = WARPS*32;
    constexpr int WM = BM/WR, WN = BN/WC, FR = WM/16, FC = WN/16;
    static_assert(WN == 32, "epilogue assumes WN==32");
    constexpr int NM = (TERMS == 3) ? 2 : 1;
    constexpr int AROWS = BM*40;
    constexpr int WROWS = BN*40;
    constexpr int BUFB = (NM*AROWS + NM*WROWS)*2;
    constexpr int SLOTS = (NM*BM + NM*BN)*2;

    extern __shared__ __align__(128) char s[];
    const uint32_t sb = smem_to_u32(s);
    const int tid = threadIdx.x, wid = tid >> 5, lane = tid & 31;
    const int m0 = blockIdx.y * BM, n0 = blockIdx.x * BN;
    const int wr = wid / WC, wc = wid % WC;

    wmma::fragment<wmma::accumulator,16,16,16,float> acc[FR][FC];
    #pragma unroll
    for (int r = 0; r < FR; r++)
        #pragma unroll
        for (int t = 0; t < FC; t++) wmma::fill_fragment(acc[r][t], 0.f);

    auto stage = [&](int c, int buf) {
        const int kk = c * 32;
        #pragma unroll
        for (int sl = tid; sl < SLOTS; sl += THREADS) {
            int half = sl & 1, rowid = sl >> 1;
            const __nv_bfloat16* src; uint32_t dst;
            if (rowid < BM) {
                src = Ah + (size_t)(m0 + rowid)*K;
                dst = sb + buf*BUFB + rowid*80;
            } else if (TERMS == 3 && rowid < 2*BM) {
                int r2 = rowid - BM;
                src = Al + (size_t)(m0 + r2)*K;
                dst = sb + buf*BUFB + AROWS*2 + r2*80;
            } else if (rowid < NM*BM + BN) {
                int r2 = rowid - NM*BM;
                src = Wh + (size_t)(n0 + r2)*K;
                dst = sb + buf*BUFB + NM*AROWS*2 + r2*80;
            } else {
                int r2 = rowid - NM*BM - BN;
                src = Wl + (size_t)(n0 + r2)*K;
                dst = sb + buf*BUFB + NM*AROWS*2 + WROWS*2 + r2*80;
            }
            cpasync16(dst + half*32,      src + kk + half*16);
            cpasync16(dst + half*32 + 16, src + kk + half*16 + 8);
        }
        asm volatile("cp.async.commit_group;" ::: "memory");
    };

    const int nc = K >> 5;
    stage(0, 0);
    stage(1, 1);

    for (int c = 0; c < nc; c++) {
        if (c + 2 < nc) stage(c + 2, (c + 2) & 3);
        if (c + 2 < nc)       asm volatile("cp.async.wait_group 2;" ::: "memory");
        else if (c + 1 < nc)  asm volatile("cp.async.wait_group 1;" ::: "memory");
        else                  asm volatile("cp.async.wait_group 0;" ::: "memory");
        __syncthreads();

        const __nv_bfloat16* sAh = (const __nv_bfloat16*)(s + (c & 3)*BUFB);
        const __nv_bfloat16* sAl = sAh + AROWS;
        const __nv_bfloat16* sWh = sAh + NM*AROWS;
        const __nv_bfloat16* sWl = sWh + WROWS;

        #pragma unroll
        for (int ks = 0; ks < 2; ks++) {
            wmma::fragment<wmma::matrix_a,16,16,16,__nv_bfloat16,wmma::row_major> af[FR];
            wmma::fragment<wmma::matrix_b,16,16,16,__nv_bfloat16,wmma::col_major> bf_[FC];
            // term 1: Ah * Wh
            #pragma unroll
            for (int r = 0; r < FR; r++)
                wmma::load_matrix_sync(af[r], sAh + (wr*WM + r*16)*40 + ks*16, 40);
            #pragma unroll
            for (int t = 0; t < FC; t++)
                wmma::load_matrix_sync(bf_[t], sWh + (wc*WN + t*16)*40 + ks*16, 40);
            #pragma unroll
            for (int r = 0; r < FR; r++)
                #pragma unroll
                for (int t = 0; t < FC; t++) wmma::mma_sync(acc[r][t], af[r], bf_[t], acc[r][t]);
            if (TERMS == 3) {
                // term 2: Ah * Wl
                #pragma unroll
                for (int t = 0; t < FC; t++)
                    wmma::load_matrix_sync(bf_[t], sWl + (wc*WN + t*16)*40 + ks*16, 40);
                #pragma unroll
                for (int r = 0; r < FR; r++)
                    #pragma unroll
                    for (int t = 0; t < FC; t++) wmma::mma_sync(acc[r][t], af[r], bf_[t], acc[r][t]);
                // term 3: Al * Wh
                #pragma unroll
                for (int r = 0; r < FR; r++)
                    wmma::load_matrix_sync(af[r], sAl + (wr*WM + r*16)*40 + ks*16, 40);
                #pragma unroll
                for (int t = 0; t < FC; t++)
                    wmma::load_matrix_sync(bf_[t], sWh + (wc*WN + t*16)*40 + ks*16, 40);
                #pragma unroll
                for (int r = 0; r < FR; r++)
                    #pragma unroll
                    for (int t = 0; t < FC; t++) wmma::mma_sync(acc[r][t], af[r], bf_[t], acc[r][t]);
            }
        }
    }
    __syncthreads();

    // epilogue
    float* ep = (float*)s + wid*16*40;
    const int rr = lane & 15, hf = lane >> 4;
    #pragma unroll
    for (int rt = 0; rt < FR; rt++) {
        wmma::store_matrix_sync(ep,      acc[rt][0], 40, wmma::mem_row_major);
        wmma::store_matrix_sync(ep + 16, acc[rt][1], 40, wmma::mem_row_major);
        __syncwarp();
        const int m = m0 + wr*WM + rt*16 + rr;
        #pragma unroll
        for (int q = 0; q < 4; q++) {
            const int n = n0 + wc*WN + hf*16 + q*4;
            float4 v = *(float4*)&ep[rr*40 + hf*16 + q*4];
            float4 bv = *(const float4*)&bias[n];
            v.x += bv.x; v.y += bv.y; v.z += bv.z; v.w += bv.w;
            if (res) {
                float4 rv = *(const float4*)&res[(size_t)m*Ndim + n];
                v.x += rv.x; v.y += rv.y; v.z += rv.z; v.w += rv.w;
            }
            if (relu) {
                v.x = fmaxf(v.x, 0.f); v.y = fmaxf(v.y, 0.f);
                v.z = fmaxf(v.z, 0.f); v.w = fmaxf(v.w, 0.f);
            }
            if (Kb) {
                if (n < 256) {
                    *(float4*)&Cf[(size_t)m*Ndim + n] = v;
                } else {
                    __nv_bfloat162 b0 = __floats2bfloat162_rn(v.x, v.y);
                    __nv_bfloat162 b1 = __floats2bfloat162_rn(v.z, v.w);
                    __nv_bfloat16* dstb = (n < 512) ? Kb : Vb;
                    int nn = (n < 512) ? (n - 256) : (n - 512);
                    *(__nv_bfloat162*)&dstb[(size_t)m*256 + nn]     = b0;
                    *(__nv_bfloat162*)&dstb[(size_t)m*256 + nn + 2] = b1;
                }
            } else {
                if (Cf) *(float4*)&Cf[(size_t)m*Ndim + n] = v;
                if (Ch) {
                    __nv_bfloat162 h0, l0, h1, l1;
                    split2(v.x, v.y, h0, l0);
                    split2(v.z, v.w, h1, l1);
                    *(__nv_bfloat162*)&Ch[(size_t)m*Ndim + n]     = h0;
                    *(__nv_bfloat162*)&Ch[(size_t)m*Ndim + n + 2] = h1;
                    *(__nv_bfloat162*)&Cl[(size_t)m*Ndim + n]     = l0;
                    *(__nv_bfloat162*)&Cl[(size_t)m*Ndim + n + 2] = l1;
                }
            }
        }
        __syncwarp();
    }
}

// ---------------- 4) sparse attention: K+V tiles in smem ----------------------------
// dyn smem: ks @0 (512*80B = 40960, padded rows), vs @40960 (32768),
//           sq @73728 (1024), sp @74752 (3328), si @78080 (3328), embs @81408 (32)
#define AT_SMEM 81440
__global__ void __launch_bounds__(256, 2) attn_sparse(const float* __restrict__ emb_spd)
{
    extern __shared__ __align__(16) char as[];
    char* ks   = as;                       // K rows padded to 80 B
    __nv_bfloat16* vs = (__nv_bfloat16*)(as + 40960);
    float (*sq)[32]  = (float(*)[32])(as + 73728);
    float (*sp)[104] = (float(*)[104])(as + 74752);
    int   (*si)[104] = (int(*)[104])(as + 78080);
    float* embs = (float*)(as + 81408);

    const int tid = threadIdx.x, lane = tid & 31, w = tid >> 5;
    const int qc = blockIdx.x, h = blockIdx.y, b = blockIdx.z;
    const float scale = 0.17677669529663687f;

    // cooperative K tile load into padded rows + V tile load
    #pragma unroll
    for (int i = tid; i < 2048; i += 256) {
        int row = i >> 2, seg = i & 3;
        uint4 kv = *(const uint4*)&g_kb[(size_t)(b*Nn + row)*256 + h*32 + seg*8];
        *(uint4*)(ks + row*80 + seg*16) = kv;
        ((uint4*)vs)[i] = *(const uint4*)&g_vb[(size_t)(b*Nn + row)*256 + h*32 + seg*8];
    }
    if (tid < 7) embs[tid] = emb_spd[tid*Hh + h];
    __syncthreads();

    for (int qi = 0; qi < 16; qi++) {
        const int q = qc*128 + w*16 + qi;
        const int row = b*Nn + q;

        sq[w][lane] = g_qkv[(size_t)row*768 + h*32 + lane];
        __syncwarp();

        float sc[4];
        int   jj[4];
        float mx = -INFINITY;
        #pragma unroll
        for (int r = 0; r < 4; r++) {
            const int t = lane + r*32;
            sc[r] = -INFINITY; jj[r] = 0;
            if (t < TOPK) {
                int pk = g_topkidx[(size_t)row*104 + t];
                int j = pk & 0xFFFF;
                jj[r] = j;
                float dot = 0.f;
                #pragma unroll
                for (int g2 = 0; g2 < 4; g2++) {
                    uint4 kv = *(const uint4*)(ks + j*80 + g2*16);
                    unsigned int kw[4] = {kv.x, kv.y, kv.z, kv.w};
                    #pragma unroll
                    for (int p4 = 0; p4 < 4; p4++) {
                        float2 f = __bfloat1622float2(*(__nv_bfloat162*)&kw[p4]);
                        dot += sq[w][g2*8 + p4*2]     * f.x
                             + sq[w][g2*8 + p4*2 + 1] * f.y;
                    }
                }
                sc[r] = dot*scale + embs[pk >> 16];
                mx = fmaxf(mx, sc[r]);
            }
        }
        #pragma unroll
        for (int o = 16; o; o >>= 1) mx = fmaxf(mx, __shfl_xor_sync(0xFFFFFFFFu, mx, o));
        float e = 0.f;
        #pragma unroll
        for (int r = 0; r < 4; r++) {
            const int t = lane + r*32;
            if (t < TOPK) {
                float p = __expf(sc[r] - mx);
                e += p;
                sp[w][t] = p;
                si[w][t] = jj[r];
            }
        }
        #pragma unroll
        for (int o = 16; o; o >>= 1) e += __shfl_xor_sync(0xFFFFFFFFu, e, o);
        __syncwarp();

        float acc = 0.f;
        #pragma unroll 6
        for (int t = 0; t < TOPK; t++) {
            int j = si[w][t];
            acc += sp[w][t] * __bfloat162float(vs[j*32 + lane]);
        }
        float v = acc / e;
        __nv_bfloat16 hh = __float2bfloat16(v);
        size_t oidx = (size_t)row*Ee + h*32 + lane;
        g_ctxh[oidx] = hh;
        g_ctxl[oidx] = __float2bfloat16(v - __bfloat162float(hh));
        __syncwarp();
    }
}

// ---------------- 5) LayerNorm (+ optional bf16 out, + optional pool score) ---------
__global__ void ln_kernel(const float* __restrict__ in, const float* __restrict__ g,
                          const float* __restrict__ be, float* __restrict__ out,
                          __nv_bfloat16* __restrict__ oh,
                          const float* __restrict__ wp, const float* __restrict__ bp,
                          float* __restrict__ scout)
{
    __shared__ float red[16];
    const int row = blockIdx.x, tid = threadIdx.x;
    float v = in[(size_t)row*Ee + tid];
    float s = v, sq = v*v;
    #pragma unroll
    for (int o = 16; o; o >>= 1) {
        s  += __shfl_xor_sync(0xFFFFFFFFu, s,  o);
        sq += __shfl_xor_sync(0xFFFFFFFFu, sq, o);
    }
    int wid = tid >> 5, lane = tid & 31;
    if (lane == 0) { red[wid] = s; red[8 + wid] = sq; }
    __syncthreads();
    if (tid == 0) {
        float ts = 0.f, tq = 0.f;
        #pragma unroll
        for (int w2 = 0; w2 < 8; w2++) { ts += red[w2]; tq += red[8 + w2]; }
        red[0] = ts; red[8] = tq;
    }
    __syncthreads();
    float mean = red[0] * (1.f/Ee);
    float var  = red[8] * (1.f/Ee) - mean*mean;
    float rstd = rsqrtf(var + 1e-5f);
    float ov = (v - mean) * rstd * g[tid] + be[tid];
    out[(size_t)row*Ee + tid] = ov;
    if (oh) oh[(size_t)row*Ee + tid] = __float2bfloat16(ov);
    if (scout) {
        float d = ov * wp[tid];
        #pragma unroll
        for (int o = 16; o; o >>= 1) d += __shfl_xor_sync(0xFFFFFFFFu, d, o);
        __syncthreads();
        if (lane == 0) red[wid] = d;
        __syncthreads();
        if (tid == 0) {
            float t2 = 0.f;
            #pragma unroll
            for (int w2 = 0; w2 < 8; w2++) t2 += red[w2];
            scout[row] = tanhf(t2 + bp[0]);
        }
    }
}

// ---------------- 6) pooling ----------------
__global__ void __launch_bounds__(256) pool2_kernel(float* __restrict__ out)
{
    __shared__ float p[512];
    __shared__ float red[8];
    __shared__ float part[8][32];
    __shared__ float Mv, Ev;
    const int b = blockIdx.x, cc = blockIdx.y;
    const int tid = threadIdx.x, lane = tid & 31, w = tid >> 5;

    float s0 = g_score[b*Nn + tid];
    float s1 = g_score[b*Nn + 256 + tid];
    float m = fmaxf(s0, s1);
    #pragma unroll
    for (int o = 16; o; o >>= 1) m = fmaxf(m, __shfl_xor_sync(0xFFFFFFFFu, m, o));
    if (lane == 0) red[w] = m;
    __syncthreads();
    if (tid == 0) {
        float mm = -INFINITY;
        #pragma unroll
        for (int i = 0; i < 8; i++) mm = fmaxf(mm, red[i]);
        Mv = mm;
    }
    __syncthreads();
    float p0 = __expf(s0 - Mv), p1 = __expf(s1 - Mv);
    p[tid] = p0; p[tid + 256] = p1;
    float e = p0 + p1;
    #pragma unroll
    for (int o = 16; o; o >>= 1) e += __shfl_xor_sync(0xFFFFFFFFu, e, o);
    if (lane == 0) red[w] = e;
    __syncthreads();
    if (tid == 0) {
        float t = 0.f;
        #pragma unroll
        for (int i = 0; i < 8; i++) t += red[i];
        Ev = t;
    }
    __syncthreads();

    const int col = cc*32 + lane;
    float acc = 0.f;
    #pragma unroll 4
    for (int i = 0; i < 64; i++) {
        int n = w*64 + i;
        acc += p[n] * g_x2[(size_t)(b*Nn + n)*Ee + col];
    }
    part[w][lane] = acc;
    __syncthreads();
    if (w == 0) {
        float a = 0.f;
        #pragma unroll
        for (int g2 = 0; g2 < 8; g2++) a += part[g2][lane];
        out[b*Ee + col] = a / Ev;
    }
}

// ---------------- launch ----------------
extern "C" void kernel_launch(void* const* d_in, const int* in_sizes, int n_in,
                              void* d_out, int out_size)
{
    const float* x       = (const float*)d_in[0];
    const float* adj     = (const float*)d_in[1];
    const float* emb_spd = (const float*)d_in[2];
    const float* w_qkv   = (const float*)d_in[3];
    const float* b_qkv   = (const float*)d_in[4];
    const float* w_out   = (const float*)d_in[5];
    const float* b_out   = (const float*)d_in[6];
    const float* w_ff1   = (const float*)d_in[7];
    const float* b_ff1   = (const float*)d_in[8];
    const float* w_ff2   = (const float*)d_in[9];
    const float* b_ff2   = (const float*)d_in[10];
    const float* g1      = (const float*)d_in[11];
    const float* beta1   = (const float*)d_in[12];
    const float* g2      = (const float*)d_in[13];
    const float* beta2   = (const float*)d_in[14];
    const float* w_pool  = (const float*)d_in[15];
    const float* b_pool  = (const float*)d_in[16];
    float* out = (float*)d_out;

    float *p_qkv, *p_y, *p_x1, *p_score;
    cudaGetSymbolAddress((void**)&p_qkv, g_qkv);
    cudaGetSymbolAddress((void**)&p_y,   g_y);
    cudaGetSymbolAddress((void**)&p_x1,  g_x1);
    cudaGetSymbolAddress((void**)&p_score, g_score);
    float* p_x2; cudaGetSymbolAddress((void**)&p_x2, g_x2);

    __nv_bfloat16 *xh, *ctxh, *ctxl, *x1h, *ffh, *ffl, *kb, *vb;
    __nv_bfloat16 *wqkvh, *wouth, *woutl, *wff1h, *wff2h, *wff2l;
    cudaGetSymbolAddress((void**)&xh, g_xh);
    cudaGetSymbolAddress((void**)&ctxh, g_ctxh); cudaGetSymbolAddress((void**)&ctxl, g_ctxl);
    cudaGetSymbolAddress((void**)&x1h, g_x1h);
    cudaGetSymbolAddress((void**)&ffh, g_ffh);   cudaGetSymbolAddress((void**)&ffl, g_ffl);
    cudaGetSymbolAddress((void**)&kb, g_kb);     cudaGetSymbolAddress((void**)&vb, g_vb);
    cudaGetSymbolAddress((void**)&wqkvh, g_wqkvh);
    cudaGetSymbolAddress((void**)&wouth, g_wouth); cudaGetSymbolAddress((void**)&woutl, g_woutl);
    cudaGetSymbolAddress((void**)&wff1h, g_wff1h);
    cudaGetSymbolAddress((void**)&wff2h, g_wff2h); cudaGetSymbolAddress((void**)&wff2l, g_wff2l);

    auto kA1 = gemm_t<128,128,2,4,1>;   // single-term: QKV, FF1 (4 bufs, smem 81920)
    auto kB3 = gemm_t<64,64,2,2,3>;     // 3-term: out-proj, FF2 (4 bufs, smem 81920)
    cudaFuncSetAttribute(kA1, cudaFuncAttributeMaxDynamicSharedMemorySize, 81920);
    cudaFuncSetAttribute(kB3, cudaFuncAttributeMaxDynamicSharedMemorySize, 81920);
    cudaFuncSetAttribute(attn_sparse, cudaFuncAttributeMaxDynamicSharedMemorySize, AT_SMEM);

    // --- fork: graph/topology branch ---
    cudaStream_t s2;
    cudaStreamCreate(&s2);
    cudaEvent_t ev0, ev1;
    cudaEventCreateWithFlags(&ev0, cudaEventDisableTiming);
    cudaEventCreateWithFlags(&ev1, cudaEventDisableTiming);

    cudaEventRecord(ev0, 0);
    cudaStreamWaitEvent(s2, ev0, 0);
    topk_kernel<<<Bb*Nn, 512, 0, s2>>>(adj);
    bfs16_kernel<<<256, 512, 0, s2>>>();     // includes fused spd pack
    cudaEventRecord(ev1, s2);

    cvt_all<<<1792, 256>>>(x, w_qkv, w_out, w_ff1, w_ff2);
    // QKV (1-term): Q fp32, K/V bf16 direct
    kA1<<<dim3(6, 32), 256, 81920>>>(xh, nullptr, wqkvh, nullptr, b_qkv, nullptr,
                                     p_qkv, nullptr, nullptr, kb, vb, 256, 768, 0);
    cudaStreamWaitEvent(0, ev1, 0);     // join topo branch before attention
    attn_sparse<<<dim3(4, 8, 8), 256, AT_SMEM>>>(emb_spd);
    // out-proj + residual (3-term, trunk precision)
    kB3<<<dim3(4, 64), 128, 81920>>>(ctxh, ctxl, wouth, woutl, b_out, x,
                                     p_y, nullptr, nullptr, nullptr, nullptr, 256, 256, 0);
    ln_kernel<<<Mrows, 256>>>(p_y, g1, beta1, p_x1, x1h, nullptr, nullptr, nullptr);
    // FF1 + relu (1-term) -> split h/l out
    kA1<<<dim3(8, 32), 256, 81920>>>(x1h, nullptr, wff1h, nullptr, b_ff1, nullptr,
                                     nullptr, ffh, ffl, nullptr, nullptr, 256, 1024, 1);
    // FF2 + residual (3-term, trunk precision)
    kB3<<<dim3(4, 64), 128, 81920>>>(ffh, ffl, wff2h, wff2l, b_ff2, p_x1,
                                     p_y, nullptr, nullptr, nullptr, nullptr, 1024, 256, 0);
    // LN2 + fused pool score
    ln_kernel<<<Mrows, 256>>>(p_y, g2, beta2, p_x2, nullptr,
                              w_pool, b_pool, p_score);
    pool2_kernel<<<dim3(8, 8), 256>>>(out);

    cudaStreamDestroy(s2);
    cudaEventDestroy(ev0);
    cudaEventDestroy(ev1);

    (void)in_sizes; (void)n_in; (void)out_size;
}

// round 17
// speedup vs baseline: 1.2976x; 1.0833x over previous
#include <cuda_runtime.h>
#include <cuda_bf16.h>
#include <mma.h>
#include <math.h>
#include <stdint.h>

using namespace nvcuda;

#define Bb 8
#define Nn 512
#define Ee 256
#define Hh 8
#define FFd 1024
#define TOPK 102
#define Mrows (Bb*Nn)   // 4096

// ---------------- device scratch ----------------
__device__ unsigned int  g_adjbits[Bb*Nn*16];
__device__ int           g_topkidx[Bb*Nn*104];   // packed: idx | (spd<<16)
__device__ unsigned char g_spd[Bb*Nn*Nn];
__device__ float         g_score[Mrows];
__device__ __align__(16) float g_qkv[Mrows*768];
__device__ __align__(16) float g_y  [Mrows*Ee];
__device__ __align__(16) float g_x1 [Mrows*Ee];
__device__ __align__(16) float g_x2 [Mrows*Ee];

__device__ __align__(16) __nv_bfloat16 g_kb  [Mrows*Ee];
__device__ __align__(16) __nv_bfloat16 g_vb  [Mrows*Ee];
__device__ __align__(16) __nv_bfloat16 g_xh  [Mrows*Ee];
__device__ __align__(16) __nv_bfloat16 g_ctxh[Mrows*Ee],  g_ctxl[Mrows*Ee];
__device__ __align__(16) __nv_bfloat16 g_x1h [Mrows*Ee];
__device__ __align__(16) __nv_bfloat16 g_ffh [Mrows*FFd];
__device__ __align__(16) __nv_bfloat16 g_wqkvh[768*256];
__device__ __align__(16) __nv_bfloat16 g_wouth[256*256],  g_woutl[256*256];
__device__ __align__(16) __nv_bfloat16 g_wff1h[1024*256];
__device__ __align__(16) __nv_bfloat16 g_wff2h[256*1024], g_wff2l[256*1024];

// ================= helpers =================
__device__ __forceinline__ uint32_t smem_to_u32(const void* p) {
    uint32_t a;
    asm("{ .reg .u64 t; cvta.to.shared.u64 t, %1; cvt.u32.u64 %0, t; }" : "=r"(a) : "l"(p));
    return a;
}
__device__ __forceinline__ void cpasync16(uint32_t sm, const void* g) {
    asm volatile("cp.async.cg.shared.global [%0], [%1], 16;" :: "r"(sm), "l"(g) : "memory");
}
__device__ __forceinline__ void split2(float a, float b, __nv_bfloat162& h, __nv_bfloat162& l) {
    h = __floats2bfloat162_rn(a, b);
    l = __floats2bfloat162_rn(a - __bfloat162float(h.x), b - __bfloat162float(h.y));
}

// ---------------- 0) fused fp32 -> bf16 convert (lo only where needed) --------------
__global__ void cvt_all(const float* __restrict__ x, const float* __restrict__ wqkv,
                        const float* __restrict__ wout, const float* __restrict__ wff1,
                        const float* __restrict__ wff2)
{
    int gid = blockIdx.x*256 + threadIdx.x;       // float4 index, total 458752
    const float* in; __nv_bfloat16 *hi, *lo = nullptr; int off;
    if      (gid < 262144) { in = x;    hi = g_xh;    off = gid; }
    else if (gid < 311296) { in = wqkv; hi = g_wqkvh; off = gid - 262144; }
    else if (gid < 327680) { in = wout; hi = g_wouth; lo = g_woutl; off = gid - 311296; }
    else if (gid < 393216) { in = wff1; hi = g_wff1h; off = gid - 327680; }
    else                   { in = wff2; hi = g_wff2h; lo = g_wff2l; off = gid - 393216; }
    float4 v = ((const float4*)in)[off];
    __nv_bfloat162 h0, l0, h1, l1;
    split2(v.x, v.y, h0, l0);
    split2(v.z, v.w, h1, l1);
    int i = off*4;
    *(__nv_bfloat162*)(hi + i)     = h0;
    *(__nv_bfloat162*)(hi + i + 2) = h1;
    if (lo) {
        *(__nv_bfloat162*)(lo + i)     = l0;
        *(__nv_bfloat162*)(lo + i + 2) = l1;
    }
}

// ---------------- 1) top-k (512 threads) ----------------------------------------------
__global__ void __launch_bounds__(512) topk_kernel(const float* __restrict__ adj)
{
    __shared__ unsigned long long keys[512];
    __shared__ unsigned int bw[16];
    const int row = blockIdx.x;
    const int tid = threadIdx.x;

    {
        unsigned int bits = __float_as_uint(adj[(size_t)row*512 + tid]);
        unsigned int ord  = bits ^ ((bits & 0x80000000u) ? 0xFFFFFFFFu : 0x80000000u);
        keys[tid] = ((unsigned long long)ord << 32) | (unsigned long long)(511 - tid);
    }
    if (tid < 16) bw[tid] = 0u;
    __syncthreads();

    for (int k = 2; k <= 512; k <<= 1) {
        for (int jj = k >> 1; jj > 0; jj >>= 1) {
            int i = tid;
            int ixj = i ^ jj;
            if (ixj > i) {
                unsigned long long a = keys[i], c = keys[ixj];
                bool up = ((i & k) == 0);
                if ((a > c) == up) { keys[i] = c; keys[ixj] = a; }
            }
            __syncthreads();
        }
    }
    if (tid < TOPK) {
        int j = 511 - (int)(keys[410 + tid] & 0xFFFFFFFFull);
        atomicOr(&bw[j >> 5], 1u << (j & 31));
        g_topkidx[(size_t)row*104 + tid] = j;
    }
    __syncthreads();
    if (tid < 16) g_adjbits[row*16 + tid] = bw[tid];
}

// ---------------- 2) BFS + fused spd-pack: 16 warps = 16 sources --------------------
__global__ void __launch_bounds__(512) bfs16_kernel()
{
    __shared__ unsigned int adjs[512*17];
    const int tid = threadIdx.x, lane = tid & 31, w = tid >> 5;
    const int blk = blockIdx.x;                 // 0..255
    const int b = blk >> 5;
    const int s0 = (blk & 31) << 4;

    #pragma unroll
    for (int k = 0; k < 16; k++)
        adjs[tid*17 + k] = g_adjbits[((size_t)(b*Nn) + tid)*16 + k];
    __syncthreads();

    const int src = s0 + w;
    const size_t spdbase = (size_t)(b*Nn + src) * Nn;

    for (int i = lane; i < 128; i += 32)
        ((unsigned int*)(g_spd + spdbase))[i] = 0u;
    __syncwarp();
    if (lane == 0) g_spd[spdbase + src] = 1;

    unsigned int visw = 0u, frow = 0u;
    if (lane < 16) {
        frow = (lane == (src >> 5)) ? (1u << (src & 31)) : 0u;
        visw = frow;
    }

    for (int level = 1; level <= 10; level++) {
        unsigned int acc[16];
        #pragma unroll
        for (int k = 0; k < 16; k++) acc[k] = 0u;

        #pragma unroll 1
        for (int wd = 0; wd < 16; wd++) {
            unsigned int bits = __shfl_sync(0xFFFFFFFFu, frow, wd);
            if ((bits >> lane) & 1u) {
                const unsigned int* row = &adjs[(wd*32 + lane)*17];
                #pragma unroll
                for (int k = 0; k < 16; k++) acc[k] |= row[k];
            }
        }
        unsigned int nv = 0u;
        #pragma unroll
        for (int k = 0; k < 16; k++) {
            unsigned int full = __reduce_or_sync(0xFFFFFFFFu, acc[k]);
            if (lane == k) nv = full & ~visw;
        }
        if (lane < 16) { visw |= nv; frow = nv; } else frow = 0u;

        unsigned int any = __reduce_or_sync(0xFFFFFFFFu, (lane < 16) ? nv : 0u);
        if (!any) break;

        unsigned char dval = (unsigned char)((level + 1 < 6) ? level + 1 : 6);
        #pragma unroll 1
        for (int wd = 0; wd < 16; wd++) {
            unsigned int bits = __shfl_sync(0xFFFFFFFFu, frow, wd);
            if ((bits >> lane) & 1u)
                g_spd[spdbase + wd*32 + lane] = dval;
        }
    }
    __syncwarp();

    // fused pack: spd index into topkidx bits [16:24)
    const size_t tbase = (size_t)(b*Nn + src) * 104;
    for (int t = lane; t < TOPK; t += 32) {
        int j = g_topkidx[tbase + t];
        int spd = g_spd[spdbase + j];
        g_topkidx[tbase + t] = j | (spd << 16);
    }
}

// ---------------- 3) pipelined bf16 wmma GEMM (TERMS = 1, 2, or 3) -------------------
// TERMS=1: Ah*Wh.  TERMS=2: Ah*Wh + Ah*Wl.  TERMS=3: + Al*Wh.
template<int BM, int BN, int WR, int WC, int TERMS>
__global__ void __launch_bounds__(WR*WC*32, 2) gemm_t(
    const __nv_bfloat16* __restrict__ Ah, const __nv_bfloat16* __restrict__ Al,
    const __nv_bfloat16* __restrict__ Wh, const __nv_bfloat16* __restrict__ Wl,
    const float* __restrict__ bias, const float* __restrict__ res,
    float* __restrict__ Cf, __nv_bfloat16* __restrict__ Ch, __nv_bfloat16* __restrict__ Cl,
    __nv_bfloat16* __restrict__ Kb, __nv_bfloat16* __restrict__ Vb,
    int K, int Ndim, int relu)
{
    constexpr int WARPS = WR*WC, THREADS = WARPS*32;
    constexpr int WM = BM/WR, WN = BN/WC, FR = WM/16, FC = WN/16;
    static_assert(WN == 32, "epilogue assumes WN==32");
    constexpr int NMA = (TERMS == 3) ? 2 : 1;
    constexpr int NMW = (TERMS >= 2) ? 2 : 1;
    constexpr int AROWS = BM*40;
    constexpr int WROWS = BN*40;
    constexpr int BUFB = (NMA*AROWS + NMW*WROWS)*2;
    constexpr int SLOTS = (NMA*BM + NMW*BN)*2;

    extern __shared__ __align__(128) char s[];
    const uint32_t sb = smem_to_u32(s);
    const int tid = threadIdx.x, wid = tid >> 5, lane = tid & 31;
    const int m0 = blockIdx.y * BM, n0 = blockIdx.x * BN;
    const int wr = wid / WC, wc = wid % WC;

    wmma::fragment<wmma::accumulator,16,16,16,float> acc[FR][FC];
    #pragma unroll
    for (int r = 0; r < FR; r++)
        #pragma unroll
        for (int t = 0; t < FC; t++) wmma::fill_fragment(acc[r][t], 0.f);

    auto stage = [&](int c, int buf) {
        const int kk = c * 32;
        #pragma unroll
        for (int sl = tid; sl < SLOTS; sl += THREADS) {
            int half = sl & 1, rowid = sl >> 1;
            const __nv_bfloat16* src; uint32_t dst;
            if (rowid < BM) {
                src = Ah + (size_t)(m0 + rowid)*K;
                dst = sb + buf*BUFB + rowid*80;
            } else if (TERMS == 3 && rowid < 2*BM) {
                int r2 = rowid - BM;
                src = Al + (size_t)(m0 + r2)*K;
                dst = sb + buf*BUFB + AROWS*2 + r2*80;
            } else if (rowid < NMA*BM + BN) {
                int r2 = rowid - NMA*BM;
                src = Wh + (size_t)(n0 + r2)*K;
                dst = sb + buf*BUFB + NMA*AROWS*2 + r2*80;
            } else {
                int r2 = rowid - NMA*BM - BN;
                src = Wl + (size_t)(n0 + r2)*K;
                dst = sb + buf*BUFB + NMA*AROWS*2 + WROWS*2 + r2*80;
            }
            cpasync16(dst + half*32,      src + kk + half*16);
            cpasync16(dst + half*32 + 16, src + kk + half*16 + 8);
        }
        asm volatile("cp.async.commit_group;" ::: "memory");
    };

    const int nc = K >> 5;
    stage(0, 0);
    stage(1, 1);

    for (int c = 0; c < nc; c++) {
        if (c + 2 < nc) stage(c + 2, (c + 2) & 3);
        if (c + 2 < nc)       asm volatile("cp.async.wait_group 2;" ::: "memory");
        else if (c + 1 < nc)  asm volatile("cp.async.wait_group 1;" ::: "memory");
        else                  asm volatile("cp.async.wait_group 0;" ::: "memory");
        __syncthreads();

        const __nv_bfloat16* sAh = (const __nv_bfloat16*)(s + (c & 3)*BUFB);
        const __nv_bfloat16* sAl = sAh + AROWS;                  // TERMS==3 only
        const __nv_bfloat16* sWh = sAh + NMA*AROWS;
        const __nv_bfloat16* sWl = sWh + WROWS;                  // TERMS>=2 only

        #pragma unroll
        for (int ks = 0; ks < 2; ks++) {
            wmma::fragment<wmma::matrix_a,16,16,16,__nv_bfloat16,wmma::row_major> af[FR];
            wmma::fragment<wmma::matrix_b,16,16,16,__nv_bfloat16,wmma::col_major> bf_[FC];
            // term 1: Ah * Wh
            #pragma unroll
            for (int r = 0; r < FR; r++)
                wmma::load_matrix_sync(af[r], sAh + (wr*WM + r*16)*40 + ks*16, 40);
            #pragma unroll
            for (int t = 0; t < FC; t++)
                wmma::load_matrix_sync(bf_[t], sWh + (wc*WN + t*16)*40 + ks*16, 40);
            #pragma unroll
            for (int r = 0; r < FR; r++)
                #pragma unroll
                for (int t = 0; t < FC; t++) wmma::mma_sync(acc[r][t], af[r], bf_[t], acc[r][t]);
            if (TERMS >= 2) {
                // term 2: Ah * Wl
                #pragma unroll
                for (int t = 0; t < FC; t++)
                    wmma::load_matrix_sync(bf_[t], sWl + (wc*WN + t*16)*40 + ks*16, 40);
                #pragma unroll
                for (int r = 0; r < FR; r++)
                    #pragma unroll
                    for (int t = 0; t < FC; t++) wmma::mma_sync(acc[r][t], af[r], bf_[t], acc[r][t]);
            }
            if (TERMS == 3) {
                // term 3: Al * Wh
                #pragma unroll
                for (int r = 0; r < FR; r++)
                    wmma::load_matrix_sync(af[r], sAl + (wr*WM + r*16)*40 + ks*16, 40);
                #pragma unroll
                for (int t = 0; t < FC; t++)
                    wmma::load_matrix_sync(bf_[t], sWh + (wc*WN + t*16)*40 + ks*16, 40);
                #pragma unroll
                for (int r = 0; r < FR; r++)
                    #pragma unroll
                    for (int t = 0; t < FC; t++) wmma::mma_sync(acc[r][t], af[r], bf_[t], acc[r][t]);
            }
        }
    }
    __syncthreads();

    // epilogue
    float* ep = (float*)s + wid*16*40;
    const int rr = lane & 15, hf = lane >> 4;
    #pragma unroll
    for (int rt = 0; rt < FR; rt++) {
        wmma::store_matrix_sync(ep,      acc[rt][0], 40, wmma::mem_row_major);
        wmma::store_matrix_sync(ep + 16, acc[rt][1], 40, wmma::mem_row_major);
        __syncwarp();
        const int m = m0 + wr*WM + rt*16 + rr;
        #pragma unroll
        for (int q = 0; q < 4; q++) {
            const int n = n0 + wc*WN + hf*16 + q*4;
            float4 v = *(float4*)&ep[rr*40 + hf*16 + q*4];
            float4 bv = *(const float4*)&bias[n];
            v.x += bv.x; v.y += bv.y; v.z += bv.z; v.w += bv.w;
            if (res) {
                float4 rv = *(const float4*)&res[(size_t)m*Ndim + n];
                v.x += rv.x; v.y += rv.y; v.z += rv.z; v.w += rv.w;
            }
            if (relu) {
                v.x = fmaxf(v.x, 0.f); v.y = fmaxf(v.y, 0.f);
                v.z = fmaxf(v.z, 0.f); v.w = fmaxf(v.w, 0.f);
            }
            if (Kb) {
                if (n < 256) {
                    *(float4*)&Cf[(size_t)m*Ndim + n] = v;
                } else {
                    __nv_bfloat162 b0 = __floats2bfloat162_rn(v.x, v.y);
                    __nv_bfloat162 b1 = __floats2bfloat162_rn(v.z, v.w);
                    __nv_bfloat16* dstb = (n < 512) ? Kb : Vb;
                    int nn = (n < 512) ? (n - 256) : (n - 512);
                    *(__nv_bfloat162*)&dstb[(size_t)m*256 + nn]     = b0;
                    *(__nv_bfloat162*)&dstb[(size_t)m*256 + nn + 2] = b1;
                }
            } else {
                if (Cf) *(float4*)&Cf[(size_t)m*Ndim + n] = v;
                if (Ch) {
                    __nv_bfloat162 h0, l0, h1, l1;
                    split2(v.x, v.y, h0, l0);
                    split2(v.z, v.w, h1, l1);
                    *(__nv_bfloat162*)&Ch[(size_t)m*Ndim + n]     = h0;
                    *(__nv_bfloat162*)&Ch[(size_t)m*Ndim + n + 2] = h1;
                    if (Cl) {
                        *(__nv_bfloat162*)&Cl[(size_t)m*Ndim + n]     = l0;
                        *(__nv_bfloat162*)&Cl[(size_t)m*Ndim + n + 2] = l1;
                    }
                }
            }
        }
        __syncwarp();
    }
}

// ---------------- 4) sparse attention: K+V tiles in smem ----------------------------
#define AT_SMEM 81440
__global__ void __launch_bounds__(256, 2) attn_sparse(const float* __restrict__ emb_spd)
{
    extern __shared__ __align__(16) char as[];
    char* ks   = as;                       // K rows padded to 80 B
    __nv_bfloat16* vs = (__nv_bfloat16*)(as + 40960);
    float (*sq)[32]  = (float(*)[32])(as + 73728);
    float (*sp)[104] = (float(*)[104])(as + 74752);
    int   (*si)[104] = (int(*)[104])(as + 78080);
    float* embs = (float*)(as + 81408);

    const int tid = threadIdx.x, lane = tid & 31, w = tid >> 5;
    const int qc = blockIdx.x, h = blockIdx.y, b = blockIdx.z;
    const float scale = 0.17677669529663687f;

    #pragma unroll
    for (int i = tid; i < 2048; i += 256) {
        int row = i >> 2, seg = i & 3;
        uint4 kv = *(const uint4*)&g_kb[(size_t)(b*Nn + row)*256 + h*32 + seg*8];
        *(uint4*)(ks + row*80 + seg*16) = kv;
        ((uint4*)vs)[i] = *(const uint4*)&g_vb[(size_t)(b*Nn + row)*256 + h*32 + seg*8];
    }
    if (tid < 7) embs[tid] = emb_spd[tid*Hh + h];
    __syncthreads();

    for (int qi = 0; qi < 16; qi++) {
        const int q = qc*128 + w*16 + qi;
        const int row = b*Nn + q;

        sq[w][lane] = g_qkv[(size_t)row*768 + h*32 + lane];
        __syncwarp();

        float sc[4];
        int   jj[4];
        float mx = -INFINITY;
        #pragma unroll
        for (int r = 0; r < 4; r++) {
            const int t = lane + r*32;
            sc[r] = -INFINITY; jj[r] = 0;
            if (t < TOPK) {
                int pk = g_topkidx[(size_t)row*104 + t];
                int j = pk & 0xFFFF;
                jj[r] = j;
                float dot = 0.f;
                #pragma unroll
                for (int g2 = 0; g2 < 4; g2++) {
                    uint4 kv = *(const uint4*)(ks + j*80 + g2*16);
                    unsigned int kw[4] = {kv.x, kv.y, kv.z, kv.w};
                    #pragma unroll
                    for (int p4 = 0; p4 < 4; p4++) {
                        float2 f = __bfloat1622float2(*(__nv_bfloat162*)&kw[p4]);
                        dot += sq[w][g2*8 + p4*2]     * f.x
                             + sq[w][g2*8 + p4*2 + 1] * f.y;
                    }
                }
                sc[r] = dot*scale + embs[pk >> 16];
                mx = fmaxf(mx, sc[r]);
            }
        }
        #pragma unroll
        for (int o = 16; o; o >>= 1) mx = fmaxf(mx, __shfl_xor_sync(0xFFFFFFFFu, mx, o));
        float e = 0.f;
        #pragma unroll
        for (int r = 0; r < 4; r++) {
            const int t = lane + r*32;
            if (t < TOPK) {
                float p = __expf(sc[r] - mx);
                e += p;
                sp[w][t] = p;
                si[w][t] = jj[r];
            }
        }
        #pragma unroll
        for (int o = 16; o; o >>= 1) e += __shfl_xor_sync(0xFFFFFFFFu, e, o);
        __syncwarp();

        float acc = 0.f;
        #pragma unroll 6
        for (int t = 0; t < TOPK; t++) {
            int j = si[w][t];
            acc += sp[w][t] * __bfloat162float(vs[j*32 + lane]);
        }
        float v = acc / e;
        __nv_bfloat16 hh = __float2bfloat16(v);
        size_t oidx = (size_t)row*Ee + h*32 + lane;
        g_ctxh[oidx] = hh;
        g_ctxl[oidx] = __float2bfloat16(v - __bfloat162float(hh));
        __syncwarp();
    }
}

// ---------------- 5) LayerNorm (+ optional bf16 out, + optional pool score) ---------
__global__ void ln_kernel(const float* __restrict__ in, const float* __restrict__ g,
                          const float* __restrict__ be, float* __restrict__ out,
                          __nv_bfloat16* __restrict__ oh,
                          const float* __restrict__ wp, const float* __restrict__ bp,
                          float* __restrict__ scout)
{
    __shared__ float red[16];
    const int row = blockIdx.x, tid = threadIdx.x;
    float v = in[(size_t)row*Ee + tid];
    float s = v, sq = v*v;
    #pragma unroll
    for (int o = 16; o; o >>= 1) {
        s  += __shfl_xor_sync(0xFFFFFFFFu, s,  o);
        sq += __shfl_xor_sync(0xFFFFFFFFu, sq, o);
    }
    int wid = tid >> 5, lane = tid & 31;
    if (lane == 0) { red[wid] = s; red[8 + wid] = sq; }
    __syncthreads();
    if (tid == 0) {
        float ts = 0.f, tq = 0.f;
        #pragma unroll
        for (int w2 = 0; w2 < 8; w2++) { ts += red[w2]; tq += red[8 + w2]; }
        red[0] = ts; red[8] = tq;
    }
    __syncthreads();
    float mean = red[0] * (1.f/Ee);
    float var  = red[8] * (1.f/Ee) - mean*mean;
    float rstd = rsqrtf(var + 1e-5f);
    float ov = (v - mean) * rstd * g[tid] + be[tid];
    out[(size_t)row*Ee + tid] = ov;
    if (oh) oh[(size_t)row*Ee + tid] = __float2bfloat16(ov);
    if (scout) {
        float d = ov * wp[tid];
        #pragma unroll
        for (int o = 16; o; o >>= 1) d += __shfl_xor_sync(0xFFFFFFFFu, d, o);
        __syncthreads();
        if (lane == 0) red[wid] = d;
        __syncthreads();
        if (tid == 0) {
            float t2 = 0.f;
            #pragma unroll
            for (int w2 = 0; w2 < 8; w2++) t2 += red[w2];
            scout[row] = tanhf(t2 + bp[0]);
        }
    }
}

// ---------------- 6) pooling ----------------
__global__ void __launch_bounds__(256) pool2_kernel(float* __restrict__ out)
{
    __shared__ float p[512];
    __shared__ float red[8];
    __shared__ float part[8][32];
    __shared__ float Mv, Ev;
    const int b = blockIdx.x, cc = blockIdx.y;
    const int tid = threadIdx.x, lane = tid & 31, w = tid >> 5;

    float s0 = g_score[b*Nn + tid];
    float s1 = g_score[b*Nn + 256 + tid];
    float m = fmaxf(s0, s1);
    #pragma unroll
    for (int o = 16; o; o >>= 1) m = fmaxf(m, __shfl_xor_sync(0xFFFFFFFFu, m, o));
    if (lane == 0) red[w] = m;
    __syncthreads();
    if (tid == 0) {
        float mm = -INFINITY;
        #pragma unroll
        for (int i = 0; i < 8; i++) mm = fmaxf(mm, red[i]);
        Mv = mm;
    }
    __syncthreads();
    float p0 = __expf(s0 - Mv), p1 = __expf(s1 - Mv);
    p[tid] = p0; p[tid + 256] = p1;
    float e = p0 + p1;
    #pragma unroll
    for (int o = 16; o; o >>= 1) e += __shfl_xor_sync(0xFFFFFFFFu, e, o);
    if (lane == 0) red[w] = e;
    __syncthreads();
    if (tid == 0) {
        float t = 0.f;
        #pragma unroll
        for (int i = 0; i < 8; i++) t += red[i];
        Ev = t;
    }
    __syncthreads();

    const int col = cc*32 + lane;
    float acc = 0.f;
    #pragma unroll 4
    for (int i = 0; i < 64; i++) {
        int n = w*64 + i;
        acc += p[n] * g_x2[(size_t)(b*Nn + n)*Ee + col];
    }
    part[w][lane] = acc;
    __syncthreads();
    if (w == 0) {
        float a = 0.f;
        #pragma unroll
        for (int g2 = 0; g2 < 8; g2++) a += part[g2][lane];
        out[b*Ee + col] = a / Ev;
    }
}

// ---------------- launch ----------------
extern "C" void kernel_launch(void* const* d_in, const int* in_sizes, int n_in,
                              void* d_out, int out_size)
{
    const float* x       = (const float*)d_in[0];
    const float* adj     = (const float*)d_in[1];
    const float* emb_spd = (const float*)d_in[2];
    const float* w_qkv   = (const float*)d_in[3];
    const float* b_qkv   = (const float*)d_in[4];
    const float* w_out   = (const float*)d_in[5];
    const float* b_out   = (const float*)d_in[6];
    const float* w_ff1   = (const float*)d_in[7];
    const float* b_ff1   = (const float*)d_in[8];
    const float* w_ff2   = (const float*)d_in[9];
    const float* b_ff2   = (const float*)d_in[10];
    const float* g1      = (const float*)d_in[11];
    const float* beta1   = (const float*)d_in[12];
    const float* g2      = (const float*)d_in[13];
    const float* beta2   = (const float*)d_in[14];
    const float* w_pool  = (const float*)d_in[15];
    const float* b_pool  = (const float*)d_in[16];
    float* out = (float*)d_out;

    float *p_qkv, *p_y, *p_x1, *p_score;
    cudaGetSymbolAddress((void**)&p_qkv, g_qkv);
    cudaGetSymbolAddress((void**)&p_y,   g_y);
    cudaGetSymbolAddress((void**)&p_x1,  g_x1);
    cudaGetSymbolAddress((void**)&p_score, g_score);
    float* p_x2; cudaGetSymbolAddress((void**)&p_x2, g_x2);

    __nv_bfloat16 *xh, *ctxh, *ctxl, *x1h, *ffh, *kb, *vb;
    __nv_bfloat16 *wqkvh, *wouth, *woutl, *wff1h, *wff2h, *wff2l;
    cudaGetSymbolAddress((void**)&xh, g_xh);
    cudaGetSymbolAddress((void**)&ctxh, g_ctxh); cudaGetSymbolAddress((void**)&ctxl, g_ctxl);
    cudaGetSymbolAddress((void**)&x1h, g_x1h);
    cudaGetSymbolAddress((void**)&ffh, g_ffh);
    cudaGetSymbolAddress((void**)&kb, g_kb);     cudaGetSymbolAddress((void**)&vb, g_vb);
    cudaGetSymbolAddress((void**)&wqkvh, g_wqkvh);
    cudaGetSymbolAddress((void**)&wouth, g_wouth); cudaGetSymbolAddress((void**)&woutl, g_woutl);
    cudaGetSymbolAddress((void**)&wff1h, g_wff1h);
    cudaGetSymbolAddress((void**)&wff2h, g_wff2h); cudaGetSymbolAddress((void**)&wff2l, g_wff2l);

    auto kA1 = gemm_t<128,128,2,4,1>;   // 1-term: QKV, FF1 (4 bufs, smem 81920)
    auto kB3 = gemm_t<64,64,2,2,3>;     // 3-term: out-proj (smem 81920)
    auto kB2 = gemm_t<64,64,2,2,2>;     // 2-term: FF2 (smem 61440)
    cudaFuncSetAttribute(kA1, cudaFuncAttributeMaxDynamicSharedMemorySize, 81920);
    cudaFuncSetAttribute(kB3, cudaFuncAttributeMaxDynamicSharedMemorySize, 81920);
    cudaFuncSetAttribute(kB2, cudaFuncAttributeMaxDynamicSharedMemorySize, 61440);
    cudaFuncSetAttribute(attn_sparse, cudaFuncAttributeMaxDynamicSharedMemorySize, AT_SMEM);

    // --- fork: graph/topology branch ---
    cudaStream_t s2;
    cudaStreamCreate(&s2);
    cudaEvent_t ev0, ev1;
    cudaEventCreateWithFlags(&ev0, cudaEventDisableTiming);
    cudaEventCreateWithFlags(&ev1, cudaEventDisableTiming);

    cudaEventRecord(ev0, 0);
    cudaStreamWaitEvent(s2, ev0, 0);
    topk_kernel<<<Bb*Nn, 512, 0, s2>>>(adj);
    bfs16_kernel<<<256, 512, 0, s2>>>();     // includes fused spd pack
    cudaEventRecord(ev1, s2);

    cvt_all<<<1792, 256>>>(x, w_qkv, w_out, w_ff1, w_ff2);
    // QKV (1-term): Q fp32, K/V bf16 direct
    kA1<<<dim3(6, 32), 256, 81920>>>(xh, nullptr, wqkvh, nullptr, b_qkv, nullptr,
                                     p_qkv, nullptr, nullptr, kb, vb, 256, 768, 0);
    cudaStreamWaitEvent(0, ev1, 0);
    attn_sparse<<<dim3(4, 8, 8), 256, AT_SMEM>>>(emb_spd);
    // out-proj + residual (3-term, trunk precision)
    kB3<<<dim3(4, 64), 128, 81920>>>(ctxh, ctxl, wouth, woutl, b_out, x,
                                     p_y, nullptr, nullptr, nullptr, nullptr, 256, 256, 0);
    ln_kernel<<<Mrows, 256>>>(p_y, g1, beta1, p_x1, x1h, nullptr, nullptr, nullptr);
    // FF1 + relu (1-term) -> ffh only
    kA1<<<dim3(8, 32), 256, 81920>>>(x1h, nullptr, wff1h, nullptr, b_ff1, nullptr,
                                     nullptr, ffh, nullptr, nullptr, nullptr, 256, 1024, 1);
    // FF2 + residual (2-term: ffh*(wh+wl))
    kB2<<<dim3(4, 64), 128, 61440>>>(ffh, nullptr, wff2h, wff2l, b_ff2, p_x1,
                                     p_y, nullptr, nullptr, nullptr, nullptr, 1024, 256, 0);
    // LN2 + fused pool score
    ln_kernel<<<Mrows, 256>>>(p_y, g2, beta2, p_x2, nullptr,
                              w_pool, b_pool, p_score);
    pool2_kernel<<<dim3(8, 8), 256>>>(out);

    cudaStreamDestroy(s2);
    cudaEventDestroy(ev0);
    cudaEventDestroy(ev1);

    (void)in_sizes; (void)n_in; (void)out_size;
}